// round 1
// baseline (speedup 1.0000x reference)
#include <cuda_runtime.h>
#include <math.h>

// FAVOR+ attention, shapes fixed by the problem:
//   B=4, N=4096, D=1024, H=16, dk=64, M=256
// Pipeline (all fp32, deterministic):
//   0) mask -> valid[] (dtype-sniffing)
//   1) qkv = x @ Wqkv^T + bqkv  -> Q,K,V in (B,H,N,dk), Q/V masked
//   2) Qf = phi(Q), Kf = phi(K)*valid   (materialized, (BH,N,M))
//   3) S_partial = Kf^T V per n-chunk (+Ksum partial), 16 chunks
//   3b) deterministic chunk reduce -> S (BH,M,dk), Ksum (BH,M)
//   4) ctx = (Qf @ S) / (Qf @ Ksum + eps) * valid -> (B,N,D)
//   5) out = ctx @ Wout^T + bout -> d_out

namespace {
constexpr int B_  = 4;
constexpr int N_  = 4096;
constexpr int D_  = 1024;
constexpr int H_  = 16;
constexpr int DK_ = 64;
constexpr int M_  = 256;
constexpr int BH_ = B_ * H_;
constexpr int CH_ = 16;   // n-chunks for S reduction
}

// -------- device scratch (static globals; no runtime allocation) --------
__device__ float g_valid[B_ * N_];                         //  64 KB
__device__ float g_Q[BH_ * N_ * DK_];                      //  67 MB
__device__ float g_K[BH_ * N_ * DK_];                      //  67 MB
__device__ float g_V[BH_ * N_ * DK_];                      //  67 MB
__device__ float g_Qf[(size_t)BH_ * N_ * M_];              // 268 MB
__device__ float g_Kf[(size_t)BH_ * N_ * M_];              // 268 MB
__device__ float g_Spart[(size_t)BH_ * CH_ * M_ * DK_];    //  67 MB
__device__ float g_Kpart[BH_ * CH_ * M_];                  //   1 MB
__device__ float g_S[BH_ * M_ * DK_];                      //   4 MB
__device__ float g_Ksum[BH_ * M_];                         //  64 KB
__device__ float g_ctx[(size_t)B_ * N_ * D_];              //  67 MB

// ===================== kernel 0: mask -> valid ==========================
// key_padding_mask originates as bool; the harness may hand it to us as
// float32, int32, or uint8. Sniff the first 4096 32-bit words (16 KB: safe
// for every candidate dtype) and canonicalize: valid = 1.0 where NOT pad.
__global__ void k_mask(const void* __restrict__ mask) {
    __shared__ int sF, sOdd;
    const int t = threadIdx.x;
    if (t == 0) { sF = 0; sOdd = 0; }
    __syncthreads();
    const unsigned* w = (const unsigned*)mask;
    for (int i = t; i < 4096; i += 256) {
        unsigned v = w[i];
        if (v == 0x3F800000u) sF = 1;              // float 1.0f seen
        else if (v != 0u && v != 1u) sOdd = 1;     // packed-byte pattern
    }
    __syncthreads();
    if (sF) {                       // float32 mask
        const float* m = (const float*)mask;
        for (int i = t; i < B_ * N_; i += 256)
            g_valid[i] = (m[i] != 0.0f) ? 0.0f : 1.0f;
    } else if (sOdd) {              // uint8 mask
        const unsigned char* m = (const unsigned char*)mask;
        for (int i = t; i < B_ * N_; i += 256)
            g_valid[i] = m[i] ? 0.0f : 1.0f;
    } else {                        // int32 mask
        const int* m = (const int*)mask;
        for (int i = t; i < B_ * N_; i += 256)
            g_valid[i] = m[i] ? 0.0f : 1.0f;
    }
}

// ============ kernel 1: QKV projection (NT SGEMM, fused split) ==========
// C(16384 x 3072) = x(16384 x 1024) @ Wqkv(3072 x 1024)^T + bqkv
// 128x128 block tile, BK=16, 256 threads, 8x8 per thread (strided mapping).
__global__ __launch_bounds__(256) void k_qkv(const float* __restrict__ A,
                                             const float* __restrict__ W,
                                             const float* __restrict__ bias) {
    __shared__ float As[16][132];
    __shared__ float Bs[16][132];
    const int t  = threadIdx.x;
    const int ty = t >> 4, tx = t & 15;
    const int rb = blockIdx.y * 128;
    const int cb = blockIdx.x * 128;

    float acc[8][8];
#pragma unroll
    for (int i = 0; i < 8; i++)
#pragma unroll
        for (int j = 0; j < 8; j++) acc[i][j] = 0.0f;

    for (int kt = 0; kt < 1024; kt += 16) {
#pragma unroll
        for (int it = 0; it < 2; it++) {
            int lin = it * 256 + t;
            int r = lin >> 2, kq = lin & 3;
            float4 va = *(const float4*)(A + (size_t)(rb + r) * 1024 + kt + kq * 4);
            As[kq * 4 + 0][r] = va.x; As[kq * 4 + 1][r] = va.y;
            As[kq * 4 + 2][r] = va.z; As[kq * 4 + 3][r] = va.w;
            float4 vb = *(const float4*)(W + (size_t)(cb + r) * 1024 + kt + kq * 4);
            Bs[kq * 4 + 0][r] = vb.x; Bs[kq * 4 + 1][r] = vb.y;
            Bs[kq * 4 + 2][r] = vb.z; Bs[kq * 4 + 3][r] = vb.w;
        }
        __syncthreads();
#pragma unroll
        for (int k = 0; k < 16; k++) {
            float a[8], bb[8];
#pragma unroll
            for (int i = 0; i < 8; i++) a[i] = As[k][ty + 16 * i];
#pragma unroll
            for (int j = 0; j < 8; j++) bb[j] = Bs[k][tx + 16 * j];
#pragma unroll
            for (int i = 0; i < 8; i++)
#pragma unroll
                for (int j = 0; j < 8; j++) acc[i][j] = fmaf(a[i], bb[j], acc[i][j]);
        }
        __syncthreads();
    }
    // epilogue: +bias, split into Q/K/V (B,H,N,dk); mask Q and V
#pragma unroll
    for (int i = 0; i < 8; i++) {
        int r = rb + ty + 16 * i;
        int bI = r >> 12, n = r & 4095;
        float vv = g_valid[r];
#pragma unroll
        for (int j = 0; j < 8; j++) {
            int c = cb + tx + 16 * j;
            float val = acc[i][j] + bias[c];
            int which = c >> 10;
            int hc = c & 1023;
            int h = hc >> 6, dk = hc & 63;
            size_t off = (((size_t)bI * H_ + h) * N_ + n) * DK_ + dk;
            if (which == 0)      g_Q[off] = val * vv;
            else if (which == 1) g_K[off] = val;
            else                 g_V[off] = val * vv;
        }
    }
}

// ================= kernel 2: phi feature map =============================
// Per (bh, 64-row n-tile): proj(64x256) = T(64x64) @ omega_h(256x64)^T,
// then row-max stabilize, exp(proj - max - 0.5||t||^2)/sqrt(M+1e-6).
// isK: read g_K, write g_Kf, multiply rows by valid.
__global__ __launch_bounds__(256) void k_phi(const float* __restrict__ omega, int isK) {
    __shared__ float Om[256][33];
    __shared__ float Qs[64][33];
    const float* In  = isK ? g_K  : g_Q;
    float*       Out = isK ? g_Kf : g_Qf;
    const int t = threadIdx.x;
    const int w = t >> 5, l = t & 31;
    const int bh = blockIdx.x;
    const int n0 = blockIdx.y * 64;
    const int h  = bh & (H_ - 1);

    float acc[8][8];
    float sq[8];
#pragma unroll
    for (int i = 0; i < 8; i++) {
        sq[i] = 0.0f;
#pragma unroll
        for (int j = 0; j < 8; j++) acc[i][j] = 0.0f;
    }

    for (int kp = 0; kp < 2; kp++) {
        const int k0 = kp * 32;
#pragma unroll
        for (int it = 0; it < 8; it++) {
            int lin = it * 256 + t;
            int m = lin >> 3, kq = lin & 7;
            float4 v = *(const float4*)(omega + ((size_t)h * M_ + m) * DK_ + k0 + kq * 4);
            Om[m][kq * 4 + 0] = v.x; Om[m][kq * 4 + 1] = v.y;
            Om[m][kq * 4 + 2] = v.z; Om[m][kq * 4 + 3] = v.w;
        }
#pragma unroll
        for (int it = 0; it < 2; it++) {
            int lin = it * 256 + t;
            int r = lin >> 3, kq = lin & 7;
            float4 v = *(const float4*)(In + ((size_t)bh * N_ + n0 + r) * DK_ + k0 + kq * 4);
            Qs[r][kq * 4 + 0] = v.x; Qs[r][kq * 4 + 1] = v.y;
            Qs[r][kq * 4 + 2] = v.z; Qs[r][kq * 4 + 3] = v.w;
        }
        __syncthreads();
#pragma unroll 8
        for (int k = 0; k < 32; k++) {
            float a[8], bb[8];
#pragma unroll
            for (int i = 0; i < 8; i++) a[i] = Qs[w * 8 + i][k];
#pragma unroll
            for (int j = 0; j < 8; j++) bb[j] = Om[l + 32 * j][k];
#pragma unroll
            for (int i = 0; i < 8; i++)
#pragma unroll
                for (int j = 0; j < 8; j++) acc[i][j] = fmaf(a[i], bb[j], acc[i][j]);
        }
#pragma unroll
        for (int i = 0; i < 8; i++) { float q = Qs[w * 8 + i][l]; sq[i] += q * q; }
        __syncthreads();
    }
    // warp-reduce sq (||t||^2 per row)
#pragma unroll
    for (int i = 0; i < 8; i++) {
        float s = sq[i];
        for (int off = 16; off; off >>= 1) s += __shfl_xor_sync(0xffffffffu, s, off);
        sq[i] = s;
    }
    const float invs = rsqrtf((float)M_ + 1e-6f);
#pragma unroll
    for (int i = 0; i < 8; i++) {
        float mx = acc[i][0];
#pragma unroll
        for (int j = 1; j < 8; j++) mx = fmaxf(mx, acc[i][j]);
        for (int off = 16; off; off >>= 1) mx = fmaxf(mx, __shfl_xor_sync(0xffffffffu, mx, off));
        const int n = n0 + w * 8 + i;
        float scale = invs;
        if (isK) scale *= g_valid[(bh >> 4) * N_ + n];
        const float e = -mx - 0.5f * sq[i];
        size_t base = ((size_t)bh * N_ + n) * M_;
#pragma unroll
        for (int j = 0; j < 8; j++)
            Out[base + l + 32 * j] = expf(acc[i][j] + e) * scale;
    }
}

// ====== kernel 3: S partials: S[m,d] += Kf[n,m]*V[n,d], Ksum[m] += Kf ====
// grid (BH, CH); each block covers 256 n-rows (8 tiles of 32).
__global__ __launch_bounds__(256) void k_spart() {
    __shared__ float Ks[32][260];
    __shared__ float Vs[32][68];
    const int t = threadIdx.x;
    const int tmg = t >> 3, tdg = t & 7;
    const int bh = blockIdx.x, ch = blockIdx.y;

    float acc[8][8];
    float ks[8];
#pragma unroll
    for (int i = 0; i < 8; i++) {
        ks[i] = 0.0f;
#pragma unroll
        for (int j = 0; j < 8; j++) acc[i][j] = 0.0f;
    }

    for (int tile = 0; tile < 8; tile++) {
        const int nb = ch * 256 + tile * 32;
#pragma unroll
        for (int it = 0; it < 8; it++) {
            int lin = it * 256 + t;
            int r = lin >> 6, mq = lin & 63;
            float4 v = *(const float4*)(g_Kf + ((size_t)bh * N_ + nb + r) * M_ + mq * 4);
            *(float4*)&Ks[r][mq * 4] = v;
        }
#pragma unroll
        for (int it = 0; it < 2; it++) {
            int lin = it * 256 + t;
            int r = lin >> 4, dq = lin & 15;
            float4 v = *(const float4*)(g_V + ((size_t)bh * N_ + nb + r) * DK_ + dq * 4);
            *(float4*)&Vs[r][dq * 4] = v;
        }
        __syncthreads();
#pragma unroll 4
        for (int n = 0; n < 32; n++) {
            float a[8], bb[8];
#pragma unroll
            for (int i = 0; i < 8; i++) a[i] = Ks[n][tmg * 8 + i];
#pragma unroll
            for (int j = 0; j < 8; j++) bb[j] = Vs[n][tdg * 8 + j];
#pragma unroll
            for (int i = 0; i < 8; i++)
#pragma unroll
                for (int j = 0; j < 8; j++) acc[i][j] = fmaf(a[i], bb[j], acc[i][j]);
            if (tdg == 0) {
#pragma unroll
                for (int i = 0; i < 8; i++) ks[i] += a[i];
            }
        }
        __syncthreads();
    }
#pragma unroll
    for (int i = 0; i < 8; i++)
#pragma unroll
        for (int j = 0; j < 8; j++)
            g_Spart[(((size_t)bh * CH_ + ch) * M_ + tmg * 8 + i) * DK_ + tdg * 8 + j] = acc[i][j];
    if (tdg == 0) {
#pragma unroll
        for (int i = 0; i < 8; i++)
            g_Kpart[((size_t)bh * CH_ + ch) * M_ + tmg * 8 + i] = ks[i];
    }
}

// ============ kernel 3b: deterministic chunk reduction ===================
__global__ void k_sreduce() {
    const int tot = BH_ * M_ * (DK_ + 1);
    int idx = blockIdx.x * 256 + threadIdx.x;
    if (idx >= tot) return;
    int bh  = idx / (M_ * (DK_ + 1));
    int rem = idx % (M_ * (DK_ + 1));
    int m = rem / (DK_ + 1);
    int d = rem % (DK_ + 1);
    if (d < DK_) {
        float s = 0.0f;
#pragma unroll
        for (int c = 0; c < CH_; c++)
            s += g_Spart[(((size_t)bh * CH_ + c) * M_ + m) * DK_ + d];
        g_S[((size_t)bh * M_ + m) * DK_ + d] = s;
    } else {
        float s = 0.0f;
#pragma unroll
        for (int c = 0; c < CH_; c++)
            s += g_Kpart[((size_t)bh * CH_ + c) * M_ + m];
        g_Ksum[(size_t)bh * M_ + m] = s;
    }
}

// ====== kernel 4: ctx = (Qf @ S) / (Qf @ Ksum + eps) * valid =============
// grid (BH, N/64); block: 64 n-rows x 64 d-cols, K=256 in 4 tiles of 64.
__global__ __launch_bounds__(256) void k_ctx() {
    __shared__ float Qs[64][68];
    __shared__ float Ss[64][68];
    __shared__ float Kss[64];
    const int t = threadIdx.x;
    const int tr = t >> 4, tc = t & 15;
    const int bh = blockIdx.x;
    const int n0 = blockIdx.y * 64;

    float acc[4][4];
    float den[4];
#pragma unroll
    for (int i = 0; i < 4; i++) {
        den[i] = 0.0f;
#pragma unroll
        for (int j = 0; j < 4; j++) acc[i][j] = 0.0f;
    }

    for (int kt = 0; kt < 4; kt++) {
        const int k0 = kt * 64;
#pragma unroll
        for (int it = 0; it < 4; it++) {
            int lin = it * 256 + t;
            int r = lin >> 4, kq = lin & 15;
            float4 v = *(const float4*)(g_Qf + ((size_t)bh * N_ + n0 + r) * M_ + k0 + kq * 4);
            *(float4*)&Qs[r][kq * 4] = v;
        }
#pragma unroll
        for (int it = 0; it < 4; it++) {
            int lin = it * 256 + t;
            int kr = lin >> 4, dq = lin & 15;
            float4 v = *(const float4*)(g_S + ((size_t)bh * M_ + k0 + kr) * DK_ + dq * 4);
            *(float4*)&Ss[kr][dq * 4] = v;
        }
        if (t < 64) Kss[t] = g_Ksum[(size_t)bh * M_ + k0 + t];
        __syncthreads();
#pragma unroll 8
        for (int k = 0; k < 64; k++) {
            float kv = Kss[k];
            float a[4], bb[4];
#pragma unroll
            for (int i = 0; i < 4; i++) a[i] = Qs[tr + 16 * i][k];
#pragma unroll
            for (int j = 0; j < 4; j++) bb[j] = Ss[k][tc + 16 * j];
#pragma unroll
            for (int i = 0; i < 4; i++) {
                den[i] = fmaf(a[i], kv, den[i]);
#pragma unroll
                for (int j = 0; j < 4; j++) acc[i][j] = fmaf(a[i], bb[j], acc[i][j]);
            }
        }
        __syncthreads();
    }
    const int bI = bh >> 4, h = bh & 15;
#pragma unroll
    for (int i = 0; i < 4; i++) {
        const int n = n0 + tr + 16 * i;
        float vv = g_valid[bI * N_ + n];
        float dn = vv / (den[i] + 1e-6f);
#pragma unroll
        for (int j = 0; j < 4; j++)
            g_ctx[((size_t)bI * N_ + n) * D_ + h * DK_ + tc + 16 * j] = acc[i][j] * dn;
    }
}

// ============= kernel 5: output projection (NT SGEMM) ====================
// out(16384 x 1024) = ctx @ Wout(1024 x 1024)^T + bout
__global__ __launch_bounds__(256) void k_out(const float* __restrict__ W,
                                             const float* __restrict__ bias,
                                             float* __restrict__ out) {
    __shared__ float As[16][132];
    __shared__ float Bs[16][132];
    const int t  = threadIdx.x;
    const int ty = t >> 4, tx = t & 15;
    const int rb = blockIdx.y * 128;
    const int cb = blockIdx.x * 128;

    float acc[8][8];
#pragma unroll
    for (int i = 0; i < 8; i++)
#pragma unroll
        for (int j = 0; j < 8; j++) acc[i][j] = 0.0f;

    for (int kt = 0; kt < 1024; kt += 16) {
#pragma unroll
        for (int it = 0; it < 2; it++) {
            int lin = it * 256 + t;
            int r = lin >> 2, kq = lin & 3;
            float4 va = *(const float4*)(g_ctx + (size_t)(rb + r) * 1024 + kt + kq * 4);
            As[kq * 4 + 0][r] = va.x; As[kq * 4 + 1][r] = va.y;
            As[kq * 4 + 2][r] = va.z; As[kq * 4 + 3][r] = va.w;
            float4 vb = *(const float4*)(W + (size_t)(cb + r) * 1024 + kt + kq * 4);
            Bs[kq * 4 + 0][r] = vb.x; Bs[kq * 4 + 1][r] = vb.y;
            Bs[kq * 4 + 2][r] = vb.z; Bs[kq * 4 + 3][r] = vb.w;
        }
        __syncthreads();
#pragma unroll
        for (int k = 0; k < 16; k++) {
            float a[8], bb[8];
#pragma unroll
            for (int i = 0; i < 8; i++) a[i] = As[k][ty + 16 * i];
#pragma unroll
            for (int j = 0; j < 8; j++) bb[j] = Bs[k][tx + 16 * j];
#pragma unroll
            for (int i = 0; i < 8; i++)
#pragma unroll
                for (int j = 0; j < 8; j++) acc[i][j] = fmaf(a[i], bb[j], acc[i][j]);
        }
        __syncthreads();
    }
#pragma unroll
    for (int i = 0; i < 8; i++) {
        int r = rb + ty + 16 * i;
#pragma unroll
        for (int j = 0; j < 8; j++) {
            int c = cb + tx + 16 * j;
            out[(size_t)r * 1024 + c] = acc[i][j] + bias[c];
        }
    }
}

// ========================= launch ========================================
extern "C" void kernel_launch(void* const* d_in, const int* in_sizes, int n_in,
                              void* d_out, int out_size) {
    (void)in_sizes; (void)n_in; (void)out_size;
    const float* x     = (const float*)d_in[0];
    const float* Wqkv  = (const float*)d_in[1];
    const float* bqkv  = (const float*)d_in[2];
    const float* Wout  = (const float*)d_in[3];
    const float* bout  = (const float*)d_in[4];
    const float* omega = (const float*)d_in[5];
    const void*  mask  = d_in[6];
    float* out = (float*)d_out;

    k_mask<<<1, 256>>>(mask);
    k_qkv<<<dim3(24, 128), 256>>>(x, Wqkv, bqkv);
    k_phi<<<dim3(BH_, N_ / 64), 256>>>(omega, 0);   // Qf
    k_phi<<<dim3(BH_, N_ / 64), 256>>>(omega, 1);   // Kf (masked)
    k_spart<<<dim3(BH_, CH_), 256>>>();
    {
        const int tot = BH_ * M_ * (DK_ + 1);
        k_sreduce<<<(tot + 255) / 256, 256>>>();
    }
    k_ctx<<<dim3(BH_, N_ / 64), 256>>>();
    k_out<<<dim3(8, 128), 256>>>(Wout, bout, out);
}

// round 5
// speedup vs baseline: 1.1923x; 1.1923x over previous
#include <cuda_runtime.h>
#include <cstdint>
#include <math.h>

// FAVOR+ attention  B=4,N=4096,D=1024,H=16,dk=64,M=256
// R5 = R4 resubmission (R4 never ran: brokered-container infra failure).
// QKV + OUT projections via mma.sync m16n8k8 TF32 (3xTF32 hi/lo split,
// fp32-class accuracy). Baseline PTX only — harness targets sm_100 (no 'a'),
// so tcgen05/TMEM is unavailable. Middle kernels = passing R1 code.

namespace {
constexpr int B_  = 4;
constexpr int N_  = 4096;
constexpr int D_  = 1024;
constexpr int H_  = 16;
constexpr int DK_ = 64;
constexpr int M_  = 256;
constexpr int BH_ = B_ * H_;
constexpr int CH_ = 16;
}

// -------- device scratch --------
__device__ float g_valid[B_ * N_];
__device__ float g_Q[BH_ * N_ * DK_];
__device__ float g_K[BH_ * N_ * DK_];
__device__ float g_V[BH_ * N_ * DK_];
__device__ float g_Qf[(size_t)BH_ * N_ * M_];
__device__ float g_Kf[(size_t)BH_ * N_ * M_];
__device__ float g_Spart[(size_t)BH_ * CH_ * M_ * DK_];
__device__ float g_Kpart[BH_ * CH_ * M_];
__device__ float g_S[BH_ * M_ * DK_];
__device__ float g_Ksum[BH_ * M_];
__device__ float g_ctx[(size_t)B_ * N_ * D_];

// ---- tf32 helpers ----
__device__ __forceinline__ void tf32_split(float f, uint32_t& h, uint32_t& l) {
    uint32_t hb;
    asm("cvt.rna.tf32.f32 %0, %1;" : "=r"(hb) : "f"(f));
    float lf = f - __uint_as_float(hb);
    uint32_t lb;
    asm("cvt.rna.tf32.f32 %0, %1;" : "=r"(lb) : "f"(lf));
    h = hb; l = lb;
}
__device__ __forceinline__ void mma_tf32(float* c, const uint32_t* a, const uint32_t* b) {
    asm volatile(
        "mma.sync.aligned.m16n8k8.row.col.f32.tf32.tf32.f32 "
        "{%0,%1,%2,%3}, {%4,%5,%6,%7}, {%8,%9}, {%0,%1,%2,%3};"
        : "+f"(c[0]), "+f"(c[1]), "+f"(c[2]), "+f"(c[3])
        : "r"(a[0]), "r"(a[1]), "r"(a[2]), "r"(a[3]), "r"(b[0]), "r"(b[1]));
}

// ============ mma.sync TF32 3x GEMM: C(128x128 tile) = A @ Bw^T ==========
// A: (16384 x 1024) row-major (mode 1 reads g_ctx). Bw: (Ncols x 1024).
// mode 0: scatter to g_Q/g_K/g_V with bias + mask; mode 1: Cp + bias.
// Fragment layout (PTX m16n8k8): a0..a3 = {(g,tg),(g+8,tg),(g,tg+4),(g+8,tg+4)},
// b0/b1 = {(tg,g),(tg+4,g)}, c0..c3 = {(g,2tg),(g,2tg+1),(g+8,2tg),(g+8,2tg+1)}.
__global__ __launch_bounds__(256) void k_gemm_mma(const float* __restrict__ A,
                                                  const float* __restrict__ Bw,
                                                  const float* __restrict__ bias,
                                                  float* __restrict__ Cp,
                                                  int mode) {
    __shared__ uint32_t Ah[16][132], Al[16][132];
    __shared__ uint32_t Bh[16][132], Bl[16][132];
    const int t = threadIdx.x;
    const int lane = t & 31, wid = t >> 5;
    const int g = lane >> 2, tg = lane & 3;
    const int wm = wid >> 2, wn = wid & 3;        // warp tile 64(m) x 32(n)
    const int rb = blockIdx.y * 128, cb = blockIdx.x * 128;
    constexpr int K = 1024;
    const float* Ap = (mode == 1) ? (const float*)g_ctx : A;

    float acc[4][4][4];
#pragma unroll
    for (int i = 0; i < 4; i++)
#pragma unroll
        for (int j = 0; j < 4; j++)
#pragma unroll
            for (int e = 0; e < 4; e++) acc[i][j][e] = 0.0f;

    for (int kt = 0; kt < K; kt += 16) {
        // ---- stage A,B k-slab (128 rows x 16 k each), pre-split tf32 hi/lo
#pragma unroll
        for (int it = 0; it < 2; it++) {
            int f = it * 256 + t;
            int r = f >> 2, q = f & 3;
            float4 va = *(const float4*)(Ap + (size_t)(rb + r) * K + kt + q * 4);
            uint32_t h, l;
            tf32_split(va.x, h, l); Ah[q*4+0][r] = h; Al[q*4+0][r] = l;
            tf32_split(va.y, h, l); Ah[q*4+1][r] = h; Al[q*4+1][r] = l;
            tf32_split(va.z, h, l); Ah[q*4+2][r] = h; Al[q*4+2][r] = l;
            tf32_split(va.w, h, l); Ah[q*4+3][r] = h; Al[q*4+3][r] = l;
            float4 vb = *(const float4*)(Bw + (size_t)(cb + r) * K + kt + q * 4);
            tf32_split(vb.x, h, l); Bh[q*4+0][r] = h; Bl[q*4+0][r] = l;
            tf32_split(vb.y, h, l); Bh[q*4+1][r] = h; Bl[q*4+1][r] = l;
            tf32_split(vb.z, h, l); Bh[q*4+2][r] = h; Bl[q*4+2][r] = l;
            tf32_split(vb.w, h, l); Bh[q*4+3][r] = h; Bl[q*4+3][r] = l;
        }
        __syncthreads();
#pragma unroll
        for (int ks = 0; ks < 2; ks++) {
            const int k0 = ks * 8;
            uint32_t ah[4][4], al[4][4], bh[4][2], bl[4][2];
#pragma unroll
            for (int i = 0; i < 4; i++) {
                const int m0 = wm * 64 + i * 16;
                ah[i][0] = Ah[k0+tg  ][m0+g];   ah[i][1] = Ah[k0+tg  ][m0+g+8];
                ah[i][2] = Ah[k0+tg+4][m0+g];   ah[i][3] = Ah[k0+tg+4][m0+g+8];
                al[i][0] = Al[k0+tg  ][m0+g];   al[i][1] = Al[k0+tg  ][m0+g+8];
                al[i][2] = Al[k0+tg+4][m0+g];   al[i][3] = Al[k0+tg+4][m0+g+8];
            }
#pragma unroll
            for (int j = 0; j < 4; j++) {
                const int n0 = wn * 32 + j * 8;
                bh[j][0] = Bh[k0+tg][n0+g];     bh[j][1] = Bh[k0+tg+4][n0+g];
                bl[j][0] = Bl[k0+tg][n0+g];     bl[j][1] = Bl[k0+tg+4][n0+g];
            }
#pragma unroll
            for (int i = 0; i < 4; i++)
#pragma unroll
                for (int j = 0; j < 4; j++) mma_tf32(acc[i][j], ah[i], bh[j]);
#pragma unroll
            for (int i = 0; i < 4; i++)
#pragma unroll
                for (int j = 0; j < 4; j++) mma_tf32(acc[i][j], ah[i], bl[j]);
#pragma unroll
            for (int i = 0; i < 4; i++)
#pragma unroll
                for (int j = 0; j < 4; j++) mma_tf32(acc[i][j], al[i], bh[j]);
        }
        __syncthreads();
    }

    // ---- epilogue
#pragma unroll
    for (int i = 0; i < 4; i++) {
        const int r0 = rb + wm * 64 + i * 16 + g;
#pragma unroll
        for (int j = 0; j < 4; j++) {
            const int c = cb + wn * 32 + j * 8 + tg * 2;
            const float b0 = bias[c], b1 = bias[c + 1];
            if (mode == 1) {
                *(float2*)(Cp + (size_t)r0 * 1024 + c) =
                    make_float2(acc[i][j][0] + b0, acc[i][j][1] + b1);
                *(float2*)(Cp + (size_t)(r0 + 8) * 1024 + c) =
                    make_float2(acc[i][j][2] + b0, acc[i][j][3] + b1);
            } else {
                const int which = c >> 10;
                const int hh = (c & 1023) >> 6;
                const int dk = c & 63;
#pragma unroll
                for (int half = 0; half < 2; half++) {
                    const int r = r0 + half * 8;
                    const float vv = g_valid[r];
                    const float v0 = acc[i][j][half * 2 + 0] + b0;
                    const float v1 = acc[i][j][half * 2 + 1] + b1;
                    size_t off = ((((size_t)(r >> 12)) * H_ + hh) * N_ + (r & 4095)) * DK_ + dk;
                    if (which == 0)
                        *(float2*)(g_Q + off) = make_float2(v0 * vv, v1 * vv);
                    else if (which == 1)
                        *(float2*)(g_K + off) = make_float2(v0, v1);
                    else
                        *(float2*)(g_V + off) = make_float2(v0 * vv, v1 * vv);
                }
            }
        }
    }
}

// ===================== kernel 0: mask -> valid ==========================
__global__ void k_mask(const void* __restrict__ mask) {
    __shared__ int sF, sOdd;
    const int t = threadIdx.x;
    if (t == 0) { sF = 0; sOdd = 0; }
    __syncthreads();
    const unsigned* w = (const unsigned*)mask;
    for (int i = t; i < 4096; i += 256) {
        unsigned v = w[i];
        if (v == 0x3F800000u) sF = 1;
        else if (v != 0u && v != 1u) sOdd = 1;
    }
    __syncthreads();
    if (sF) {
        const float* m = (const float*)mask;
        for (int i = t; i < B_ * N_; i += 256)
            g_valid[i] = (m[i] != 0.0f) ? 0.0f : 1.0f;
    } else if (sOdd) {
        const unsigned char* m = (const unsigned char*)mask;
        for (int i = t; i < B_ * N_; i += 256)
            g_valid[i] = m[i] ? 0.0f : 1.0f;
    } else {
        const int* m = (const int*)mask;
        for (int i = t; i < B_ * N_; i += 256)
            g_valid[i] = m[i] ? 0.0f : 1.0f;
    }
}

// ================= kernel 2: phi feature map =============================
__global__ __launch_bounds__(256) void k_phi(const float* __restrict__ omega, int isK) {
    __shared__ float Om[256][33];
    __shared__ float Qs[64][33];
    const float* In  = isK ? g_K  : g_Q;
    float*       Out = isK ? g_Kf : g_Qf;
    const int t = threadIdx.x;
    const int w = t >> 5, l = t & 31;
    const int bh = blockIdx.x;
    const int n0 = blockIdx.y * 64;
    const int h  = bh & (H_ - 1);

    float acc[8][8];
    float sq[8];
#pragma unroll
    for (int i = 0; i < 8; i++) {
        sq[i] = 0.0f;
#pragma unroll
        for (int j = 0; j < 8; j++) acc[i][j] = 0.0f;
    }

    for (int kp = 0; kp < 2; kp++) {
        const int k0 = kp * 32;
#pragma unroll
        for (int it = 0; it < 8; it++) {
            int lin = it * 256 + t;
            int m = lin >> 3, kq = lin & 7;
            float4 v = *(const float4*)(omega + ((size_t)h * M_ + m) * DK_ + k0 + kq * 4);
            Om[m][kq * 4 + 0] = v.x; Om[m][kq * 4 + 1] = v.y;
            Om[m][kq * 4 + 2] = v.z; Om[m][kq * 4 + 3] = v.w;
        }
#pragma unroll
        for (int it = 0; it < 2; it++) {
            int lin = it * 256 + t;
            int r = lin >> 3, kq = lin & 7;
            float4 v = *(const float4*)(In + ((size_t)bh * N_ + n0 + r) * DK_ + k0 + kq * 4);
            Qs[r][kq * 4 + 0] = v.x; Qs[r][kq * 4 + 1] = v.y;
            Qs[r][kq * 4 + 2] = v.z; Qs[r][kq * 4 + 3] = v.w;
        }
        __syncthreads();
#pragma unroll 8
        for (int k = 0; k < 32; k++) {
            float a[8], bb[8];
#pragma unroll
            for (int i = 0; i < 8; i++) a[i] = Qs[w * 8 + i][k];
#pragma unroll
            for (int j = 0; j < 8; j++) bb[j] = Om[l + 32 * j][k];
#pragma unroll
            for (int i = 0; i < 8; i++)
#pragma unroll
                for (int j = 0; j < 8; j++) acc[i][j] = fmaf(a[i], bb[j], acc[i][j]);
        }
#pragma unroll
        for (int i = 0; i < 8; i++) { float q = Qs[w * 8 + i][l]; sq[i] += q * q; }
        __syncthreads();
    }
#pragma unroll
    for (int i = 0; i < 8; i++) {
        float s = sq[i];
        for (int off = 16; off; off >>= 1) s += __shfl_xor_sync(0xffffffffu, s, off);
        sq[i] = s;
    }
    const float invs = rsqrtf((float)M_ + 1e-6f);
#pragma unroll
    for (int i = 0; i < 8; i++) {
        float mx = acc[i][0];
#pragma unroll
        for (int j = 1; j < 8; j++) mx = fmaxf(mx, acc[i][j]);
        for (int off = 16; off; off >>= 1) mx = fmaxf(mx, __shfl_xor_sync(0xffffffffu, mx, off));
        const int n = n0 + w * 8 + i;
        float scale = invs;
        if (isK) scale *= g_valid[(bh >> 4) * N_ + n];
        const float e = -mx - 0.5f * sq[i];
        size_t base = ((size_t)bh * N_ + n) * M_;
#pragma unroll
        for (int j = 0; j < 8; j++)
            Out[base + l + 32 * j] = expf(acc[i][j] + e) * scale;
    }
}

// ====== kernel 3: S partials ============================================
__global__ __launch_bounds__(256) void k_spart() {
    __shared__ float Ks[32][260];
    __shared__ float Vs[32][68];
    const int t = threadIdx.x;
    const int tmg = t >> 3, tdg = t & 7;
    const int bh = blockIdx.x, ch = blockIdx.y;

    float acc[8][8];
    float ks[8];
#pragma unroll
    for (int i = 0; i < 8; i++) {
        ks[i] = 0.0f;
#pragma unroll
        for (int j = 0; j < 8; j++) acc[i][j] = 0.0f;
    }

    for (int tile = 0; tile < 8; tile++) {
        const int nb = ch * 256 + tile * 32;
#pragma unroll
        for (int it = 0; it < 8; it++) {
            int lin = it * 256 + t;
            int r = lin >> 6, mq = lin & 63;
            float4 v = *(const float4*)(g_Kf + ((size_t)bh * N_ + nb + r) * M_ + mq * 4);
            *(float4*)&Ks[r][mq * 4] = v;
        }
#pragma unroll
        for (int it = 0; it < 2; it++) {
            int lin = it * 256 + t;
            int r = lin >> 4, dq = lin & 15;
            float4 v = *(const float4*)(g_V + ((size_t)bh * N_ + nb + r) * DK_ + dq * 4);
            *(float4*)&Vs[r][dq * 4] = v;
        }
        __syncthreads();
#pragma unroll 4
        for (int n = 0; n < 32; n++) {
            float a[8], bb[8];
#pragma unroll
            for (int i = 0; i < 8; i++) a[i] = Ks[n][tmg * 8 + i];
#pragma unroll
            for (int j = 0; j < 8; j++) bb[j] = Vs[n][tdg * 8 + j];
#pragma unroll
            for (int i = 0; i < 8; i++)
#pragma unroll
                for (int j = 0; j < 8; j++) acc[i][j] = fmaf(a[i], bb[j], acc[i][j]);
            if (tdg == 0) {
#pragma unroll
                for (int i = 0; i < 8; i++) ks[i] += a[i];
            }
        }
        __syncthreads();
    }
#pragma unroll
    for (int i = 0; i < 8; i++)
#pragma unroll
        for (int j = 0; j < 8; j++)
            g_Spart[(((size_t)bh * CH_ + ch) * M_ + tmg * 8 + i) * DK_ + tdg * 8 + j] = acc[i][j];
    if (tdg == 0) {
#pragma unroll
        for (int i = 0; i < 8; i++)
            g_Kpart[((size_t)bh * CH_ + ch) * M_ + tmg * 8 + i] = ks[i];
    }
}

// ============ kernel 3b: deterministic chunk reduction ===================
__global__ void k_sreduce() {
    const int tot = BH_ * M_ * (DK_ + 1);
    int idx = blockIdx.x * 256 + threadIdx.x;
    if (idx >= tot) return;
    int bh  = idx / (M_ * (DK_ + 1));
    int rem = idx % (M_ * (DK_ + 1));
    int m = rem / (DK_ + 1);
    int d = rem % (DK_ + 1);
    if (d < DK_) {
        float s = 0.0f;
#pragma unroll
        for (int c = 0; c < CH_; c++)
            s += g_Spart[(((size_t)bh * CH_ + c) * M_ + m) * DK_ + d];
        g_S[((size_t)bh * M_ + m) * DK_ + d] = s;
    } else {
        float s = 0.0f;
#pragma unroll
        for (int c = 0; c < CH_; c++)
            s += g_Kpart[((size_t)bh * CH_ + c) * M_ + m];
        g_Ksum[(size_t)bh * M_ + m] = s;
    }
}

// ====== kernel 4: ctx ====================================================
__global__ __launch_bounds__(256) void k_ctx() {
    __shared__ float Qs[64][68];
    __shared__ float Ss[64][68];
    __shared__ float Kss[64];
    const int t = threadIdx.x;
    const int tr = t >> 4, tc = t & 15;
    const int bh = blockIdx.x;
    const int n0 = blockIdx.y * 64;

    float acc[4][4];
    float den[4];
#pragma unroll
    for (int i = 0; i < 4; i++) {
        den[i] = 0.0f;
#pragma unroll
        for (int j = 0; j < 4; j++) acc[i][j] = 0.0f;
    }

    for (int kt = 0; kt < 4; kt++) {
        const int k0 = kt * 64;
#pragma unroll
        for (int it = 0; it < 4; it++) {
            int lin = it * 256 + t;
            int r = lin >> 4, kq = lin & 15;
            float4 v = *(const float4*)(g_Qf + ((size_t)bh * N_ + n0 + r) * M_ + k0 + kq * 4);
            *(float4*)&Qs[r][kq * 4] = v;
        }
#pragma unroll
        for (int it = 0; it < 4; it++) {
            int lin = it * 256 + t;
            int kr = lin >> 4, dq = lin & 15;
            float4 v = *(const float4*)(g_S + ((size_t)bh * M_ + k0 + kr) * DK_ + dq * 4);
            *(float4*)&Ss[kr][dq * 4] = v;
        }
        if (t < 64) Kss[t] = g_Ksum[(size_t)bh * M_ + k0 + t];
        __syncthreads();
#pragma unroll 8
        for (int k = 0; k < 64; k++) {
            float kv = Kss[k];
            float a[4], bb[4];
#pragma unroll
            for (int i = 0; i < 4; i++) a[i] = Qs[tr + 16 * i][k];
#pragma unroll
            for (int j = 0; j < 4; j++) bb[j] = Ss[k][tc + 16 * j];
#pragma unroll
            for (int i = 0; i < 4; i++) {
                den[i] = fmaf(a[i], kv, den[i]);
#pragma unroll
                for (int j = 0; j < 4; j++) acc[i][j] = fmaf(a[i], bb[j], acc[i][j]);
            }
        }
        __syncthreads();
    }
    const int bI = bh >> 4, h = bh & 15;
#pragma unroll
    for (int i = 0; i < 4; i++) {
        const int n = n0 + tr + 16 * i;
        float vv = g_valid[bI * N_ + n];
        float dn = vv / (den[i] + 1e-6f);
#pragma unroll
        for (int j = 0; j < 4; j++)
            g_ctx[((size_t)bI * N_ + n) * D_ + h * DK_ + tc + 16 * j] = acc[i][j] * dn;
    }
}

// ========================= launch ========================================
extern "C" void kernel_launch(void* const* d_in, const int* in_sizes, int n_in,
                              void* d_out, int out_size) {
    (void)in_sizes; (void)n_in; (void)out_size;
    const float* x     = (const float*)d_in[0];
    const float* Wqkv  = (const float*)d_in[1];
    const float* bqkv  = (const float*)d_in[2];
    const float* Wout  = (const float*)d_in[3];
    const float* bout  = (const float*)d_in[4];
    const float* omega = (const float*)d_in[5];
    const void*  mask  = d_in[6];
    float* out = (float*)d_out;

    k_mask<<<1, 256>>>(mask);
    k_gemm_mma<<<dim3(24, 128), 256>>>(x, Wqkv, bqkv, nullptr, 0);
    k_phi<<<dim3(BH_, N_ / 64), 256>>>(omega, 0);
    k_phi<<<dim3(BH_, N_ / 64), 256>>>(omega, 1);
    k_spart<<<dim3(BH_, CH_), 256>>>();
    {
        const int tot = BH_ * M_ * (DK_ + 1);
        k_sreduce<<<(tot + 255) / 256, 256>>>();
    }
    k_ctx<<<dim3(BH_, N_ / 64), 256>>>();
    k_gemm_mma<<<dim3(8, 128), 256>>>(x, Wout, bout, out, 1);
}

// round 6
// speedup vs baseline: 1.3204x; 1.1075x over previous
#include <cuda_runtime.h>
#include <cstdint>
#include <math.h>

// FAVOR+ attention  B=4,N=4096,D=1024,H=16,dk=64,M=256
// R6: GEMM mainloop rebuilt: cp.async double-buffered raw-f32 staging,
// tf32 hi/lo split moved to register-side fragment loads (3xTF32 accuracy).
// Fragment<->C mapping identical to passing R5. Middle kernels unchanged.

namespace {
constexpr int B_  = 4;
constexpr int N_  = 4096;
constexpr int D_  = 1024;
constexpr int H_  = 16;
constexpr int DK_ = 64;
constexpr int M_  = 256;
constexpr int BH_ = B_ * H_;
constexpr int CH_ = 16;
}

// -------- device scratch --------
__device__ float g_valid[B_ * N_];
__device__ float g_Q[BH_ * N_ * DK_];
__device__ float g_K[BH_ * N_ * DK_];
__device__ float g_V[BH_ * N_ * DK_];
__device__ float g_Qf[(size_t)BH_ * N_ * M_];
__device__ float g_Kf[(size_t)BH_ * N_ * M_];
__device__ float g_Spart[(size_t)BH_ * CH_ * M_ * DK_];
__device__ float g_Kpart[BH_ * CH_ * M_];
__device__ float g_S[BH_ * M_ * DK_];
__device__ float g_Ksum[BH_ * M_];
__device__ float g_ctx[(size_t)B_ * N_ * D_];

// ---- helpers ----
__device__ __forceinline__ uint32_t smem_u32(const void* p) {
    uint32_t a;
    asm("{ .reg .u64 t; cvta.to.shared.u64 t, %1; cvt.u32.u64 %0, t; }"
        : "=r"(a) : "l"(p));
    return a;
}
__device__ __forceinline__ void cp_async16(void* sdst, const void* gsrc) {
    asm volatile("cp.async.cg.shared.global [%0], [%1], 16;"
                 :: "r"(smem_u32(sdst)), "l"(gsrc) : "memory");
}
__device__ __forceinline__ void tf32_split(float f, uint32_t& h, uint32_t& l) {
    uint32_t hb;
    asm("cvt.rna.tf32.f32 %0, %1;" : "=r"(hb) : "f"(f));
    float lf = f - __uint_as_float(hb);
    uint32_t lb;
    asm("cvt.rna.tf32.f32 %0, %1;" : "=r"(lb) : "f"(lf));
    h = hb; l = lb;
}
__device__ __forceinline__ void mma_tf32(float* c, const uint32_t* a, const uint32_t* b) {
    asm volatile(
        "mma.sync.aligned.m16n8k8.row.col.f32.tf32.tf32.f32 "
        "{%0,%1,%2,%3}, {%4,%5,%6,%7}, {%8,%9}, {%0,%1,%2,%3};"
        : "+f"(c[0]), "+f"(c[1]), "+f"(c[2]), "+f"(c[3])
        : "r"(a[0]), "r"(a[1]), "r"(a[2]), "r"(a[3]), "r"(b[0]), "r"(b[1]));
}

// ============ mma.sync TF32 3x GEMM: C(128x128 tile) = A @ Bw^T ==========
// A: (16384 x 1024) row-major (mode 1 reads g_ctx). Bw: (Ncols x 1024).
// cp.async double-buffered raw-f32 smem; split to tf32 hi/lo in registers.
// Fragment layout (PTX m16n8k8): a0..a3 = {(g,tg),(g+8,tg),(g,tg+4),(g+8,tg+4)},
// b0/b1 = {(tg,g),(tg+4,g)}, c0..c3 = {(g,2tg),(g,2tg+1),(g+8,2tg),(g+8,2tg+1)}.
__global__ __launch_bounds__(256) void k_gemm_mma(const float* __restrict__ A,
                                                  const float* __restrict__ Bw,
                                                  const float* __restrict__ bias,
                                                  float* __restrict__ Cp,
                                                  int mode) {
    __shared__ __align__(16) float As[2][128][20];   // [stage][m][k], pad 20
    __shared__ __align__(16) float Bs[2][128][20];
    const int t = threadIdx.x;
    const int lane = t & 31, wid = t >> 5;
    const int g = lane >> 2, tg = lane & 3;
    const int wm = wid >> 2, wn = wid & 3;           // warp tile 64(m) x 32(n)
    const int rb = blockIdx.y * 128, cb = blockIdx.x * 128;
    constexpr int K = 1024;
    constexpr int NSLAB = K / 16;                    // 64
    const float* Ap = (mode == 1) ? (const float*)g_ctx : A;

    float acc[4][4][4];
#pragma unroll
    for (int i = 0; i < 4; i++)
#pragma unroll
        for (int j = 0; j < 4; j++)
#pragma unroll
            for (int e = 0; e < 4; e++) acc[i][j][e] = 0.0f;

    // prefetch slab 0
    {
#pragma unroll
        for (int it = 0; it < 2; it++) {
            int f = it * 256 + t;
            int r = f >> 2, q = f & 3;
            cp_async16(&As[0][r][q * 4], Ap + (size_t)(rb + r) * K + q * 4);
            cp_async16(&Bs[0][r][q * 4], Bw + (size_t)(cb + r) * K + q * 4);
        }
        asm volatile("cp.async.commit_group;" ::: "memory");
    }

    for (int sl = 0; sl < NSLAB; sl++) {
        const int st = sl & 1;
        if (sl + 1 < NSLAB) {
            const int kt = (sl + 1) * 16;
            const int ns = st ^ 1;
#pragma unroll
            for (int it = 0; it < 2; it++) {
                int f = it * 256 + t;
                int r = f >> 2, q = f & 3;
                cp_async16(&As[ns][r][q * 4], Ap + (size_t)(rb + r) * K + kt + q * 4);
                cp_async16(&Bs[ns][r][q * 4], Bw + (size_t)(cb + r) * K + kt + q * 4);
            }
            asm volatile("cp.async.commit_group;" ::: "memory");
            asm volatile("cp.async.wait_group 1;" ::: "memory");
        } else {
            asm volatile("cp.async.wait_group 0;" ::: "memory");
        }
        __syncthreads();

#pragma unroll
        for (int ks = 0; ks < 2; ks++) {
            const int k0 = ks * 8;
            uint32_t ah[4][4], al[4][4], bh[4][2], bl[4][2];
#pragma unroll
            for (int i = 0; i < 4; i++) {
                const int m0 = wm * 64 + i * 16;
                tf32_split(As[st][m0 + g    ][k0 + tg    ], ah[i][0], al[i][0]);
                tf32_split(As[st][m0 + g + 8][k0 + tg    ], ah[i][1], al[i][1]);
                tf32_split(As[st][m0 + g    ][k0 + tg + 4], ah[i][2], al[i][2]);
                tf32_split(As[st][m0 + g + 8][k0 + tg + 4], ah[i][3], al[i][3]);
            }
#pragma unroll
            for (int j = 0; j < 4; j++) {
                const int n0 = wn * 32 + j * 8;
                tf32_split(Bs[st][n0 + g][k0 + tg    ], bh[j][0], bl[j][0]);
                tf32_split(Bs[st][n0 + g][k0 + tg + 4], bh[j][1], bl[j][1]);
            }
#pragma unroll
            for (int i = 0; i < 4; i++)
#pragma unroll
                for (int j = 0; j < 4; j++) mma_tf32(acc[i][j], ah[i], bh[j]);
#pragma unroll
            for (int i = 0; i < 4; i++)
#pragma unroll
                for (int j = 0; j < 4; j++) mma_tf32(acc[i][j], ah[i], bl[j]);
#pragma unroll
            for (int i = 0; i < 4; i++)
#pragma unroll
                for (int j = 0; j < 4; j++) mma_tf32(acc[i][j], al[i], bh[j]);
        }
        __syncthreads();
    }

    // ---- epilogue (identical to R5)
#pragma unroll
    for (int i = 0; i < 4; i++) {
        const int r0 = rb + wm * 64 + i * 16 + g;
#pragma unroll
        for (int j = 0; j < 4; j++) {
            const int c = cb + wn * 32 + j * 8 + tg * 2;
            const float b0 = bias[c], b1 = bias[c + 1];
            if (mode == 1) {
                *(float2*)(Cp + (size_t)r0 * 1024 + c) =
                    make_float2(acc[i][j][0] + b0, acc[i][j][1] + b1);
                *(float2*)(Cp + (size_t)(r0 + 8) * 1024 + c) =
                    make_float2(acc[i][j][2] + b0, acc[i][j][3] + b1);
            } else {
                const int which = c >> 10;
                const int hh = (c & 1023) >> 6;
                const int dk = c & 63;
#pragma unroll
                for (int half = 0; half < 2; half++) {
                    const int r = r0 + half * 8;
                    const float vv = g_valid[r];
                    const float v0 = acc[i][j][half * 2 + 0] + b0;
                    const float v1 = acc[i][j][half * 2 + 1] + b1;
                    size_t off = ((((size_t)(r >> 12)) * H_ + hh) * N_ + (r & 4095)) * DK_ + dk;
                    if (which == 0)
                        *(float2*)(g_Q + off) = make_float2(v0 * vv, v1 * vv);
                    else if (which == 1)
                        *(float2*)(g_K + off) = make_float2(v0, v1);
                    else
                        *(float2*)(g_V + off) = make_float2(v0 * vv, v1 * vv);
                }
            }
        }
    }
}

// ===================== kernel 0: mask -> valid ==========================
__global__ void k_mask(const void* __restrict__ mask) {
    __shared__ int sF, sOdd;
    const int t = threadIdx.x;
    if (t == 0) { sF = 0; sOdd = 0; }
    __syncthreads();
    const unsigned* w = (const unsigned*)mask;
    for (int i = t; i < 4096; i += 256) {
        unsigned v = w[i];
        if (v == 0x3F800000u) sF = 1;
        else if (v != 0u && v != 1u) sOdd = 1;
    }
    __syncthreads();
    if (sF) {
        const float* m = (const float*)mask;
        for (int i = t; i < B_ * N_; i += 256)
            g_valid[i] = (m[i] != 0.0f) ? 0.0f : 1.0f;
    } else if (sOdd) {
        const unsigned char* m = (const unsigned char*)mask;
        for (int i = t; i < B_ * N_; i += 256)
            g_valid[i] = m[i] ? 0.0f : 1.0f;
    } else {
        const int* m = (const int*)mask;
        for (int i = t; i < B_ * N_; i += 256)
            g_valid[i] = m[i] ? 0.0f : 1.0f;
    }
}

// ================= kernel 2: phi feature map =============================
__global__ __launch_bounds__(256) void k_phi(const float* __restrict__ omega, int isK) {
    __shared__ float Om[256][33];
    __shared__ float Qs[64][33];
    const float* In  = isK ? g_K  : g_Q;
    float*       Out = isK ? g_Kf : g_Qf;
    const int t = threadIdx.x;
    const int w = t >> 5, l = t & 31;
    const int bh = blockIdx.x;
    const int n0 = blockIdx.y * 64;
    const int h  = bh & (H_ - 1);

    float acc[8][8];
    float sq[8];
#pragma unroll
    for (int i = 0; i < 8; i++) {
        sq[i] = 0.0f;
#pragma unroll
        for (int j = 0; j < 8; j++) acc[i][j] = 0.0f;
    }

    for (int kp = 0; kp < 2; kp++) {
        const int k0 = kp * 32;
#pragma unroll
        for (int it = 0; it < 8; it++) {
            int lin = it * 256 + t;
            int m = lin >> 3, kq = lin & 7;
            float4 v = *(const float4*)(omega + ((size_t)h * M_ + m) * DK_ + k0 + kq * 4);
            Om[m][kq * 4 + 0] = v.x; Om[m][kq * 4 + 1] = v.y;
            Om[m][kq * 4 + 2] = v.z; Om[m][kq * 4 + 3] = v.w;
        }
#pragma unroll
        for (int it = 0; it < 2; it++) {
            int lin = it * 256 + t;
            int r = lin >> 3, kq = lin & 7;
            float4 v = *(const float4*)(In + ((size_t)bh * N_ + n0 + r) * DK_ + k0 + kq * 4);
            Qs[r][kq * 4 + 0] = v.x; Qs[r][kq * 4 + 1] = v.y;
            Qs[r][kq * 4 + 2] = v.z; Qs[r][kq * 4 + 3] = v.w;
        }
        __syncthreads();
#pragma unroll 8
        for (int k = 0; k < 32; k++) {
            float a[8], bb[8];
#pragma unroll
            for (int i = 0; i < 8; i++) a[i] = Qs[w * 8 + i][k];
#pragma unroll
            for (int j = 0; j < 8; j++) bb[j] = Om[l + 32 * j][k];
#pragma unroll
            for (int i = 0; i < 8; i++)
#pragma unroll
                for (int j = 0; j < 8; j++) acc[i][j] = fmaf(a[i], bb[j], acc[i][j]);
        }
#pragma unroll
        for (int i = 0; i < 8; i++) { float q = Qs[w * 8 + i][l]; sq[i] += q * q; }
        __syncthreads();
    }
#pragma unroll
    for (int i = 0; i < 8; i++) {
        float s = sq[i];
        for (int off = 16; off; off >>= 1) s += __shfl_xor_sync(0xffffffffu, s, off);
        sq[i] = s;
    }
    const float invs = rsqrtf((float)M_ + 1e-6f);
#pragma unroll
    for (int i = 0; i < 8; i++) {
        float mx = acc[i][0];
#pragma unroll
        for (int j = 1; j < 8; j++) mx = fmaxf(mx, acc[i][j]);
        for (int off = 16; off; off >>= 1) mx = fmaxf(mx, __shfl_xor_sync(0xffffffffu, mx, off));
        const int n = n0 + w * 8 + i;
        float scale = invs;
        if (isK) scale *= g_valid[(bh >> 4) * N_ + n];
        const float e = -mx - 0.5f * sq[i];
        size_t base = ((size_t)bh * N_ + n) * M_;
#pragma unroll
        for (int j = 0; j < 8; j++)
            Out[base + l + 32 * j] = expf(acc[i][j] + e) * scale;
    }
}

// ====== kernel 3: S partials ============================================
__global__ __launch_bounds__(256) void k_spart() {
    __shared__ float Ks[32][260];
    __shared__ float Vs[32][68];
    const int t = threadIdx.x;
    const int tmg = t >> 3, tdg = t & 7;
    const int bh = blockIdx.x, ch = blockIdx.y;

    float acc[8][8];
    float ks[8];
#pragma unroll
    for (int i = 0; i < 8; i++) {
        ks[i] = 0.0f;
#pragma unroll
        for (int j = 0; j < 8; j++) acc[i][j] = 0.0f;
    }

    for (int tile = 0; tile < 8; tile++) {
        const int nb = ch * 256 + tile * 32;
#pragma unroll
        for (int it = 0; it < 8; it++) {
            int lin = it * 256 + t;
            int r = lin >> 6, mq = lin & 63;
            float4 v = *(const float4*)(g_Kf + ((size_t)bh * N_ + nb + r) * M_ + mq * 4);
            *(float4*)&Ks[r][mq * 4] = v;
        }
#pragma unroll
        for (int it = 0; it < 2; it++) {
            int lin = it * 256 + t;
            int r = lin >> 4, dq = lin & 15;
            float4 v = *(const float4*)(g_V + ((size_t)bh * N_ + nb + r) * DK_ + dq * 4);
            *(float4*)&Vs[r][dq * 4] = v;
        }
        __syncthreads();
#pragma unroll 4
        for (int n = 0; n < 32; n++) {
            float a[8], bb[8];
#pragma unroll
            for (int i = 0; i < 8; i++) a[i] = Ks[n][tmg * 8 + i];
#pragma unroll
            for (int j = 0; j < 8; j++) bb[j] = Vs[n][tdg * 8 + j];
#pragma unroll
            for (int i = 0; i < 8; i++)
#pragma unroll
                for (int j = 0; j < 8; j++) acc[i][j] = fmaf(a[i], bb[j], acc[i][j]);
            if (tdg == 0) {
#pragma unroll
                for (int i = 0; i < 8; i++) ks[i] += a[i];
            }
        }
        __syncthreads();
    }
#pragma unroll
    for (int i = 0; i < 8; i++)
#pragma unroll
        for (int j = 0; j < 8; j++)
            g_Spart[(((size_t)bh * CH_ + ch) * M_ + tmg * 8 + i) * DK_ + tdg * 8 + j] = acc[i][j];
    if (tdg == 0) {
#pragma unroll
        for (int i = 0; i < 8; i++)
            g_Kpart[((size_t)bh * CH_ + ch) * M_ + tmg * 8 + i] = ks[i];
    }
}

// ============ kernel 3b: deterministic chunk reduction ===================
__global__ void k_sreduce() {
    const int tot = BH_ * M_ * (DK_ + 1);
    int idx = blockIdx.x * 256 + threadIdx.x;
    if (idx >= tot) return;
    int bh  = idx / (M_ * (DK_ + 1));
    int rem = idx % (M_ * (DK_ + 1));
    int m = rem / (DK_ + 1);
    int d = rem % (DK_ + 1);
    if (d < DK_) {
        float s = 0.0f;
#pragma unroll
        for (int c = 0; c < CH_; c++)
            s += g_Spart[(((size_t)bh * CH_ + c) * M_ + m) * DK_ + d];
        g_S[((size_t)bh * M_ + m) * DK_ + d] = s;
    } else {
        float s = 0.0f;
#pragma unroll
        for (int c = 0; c < CH_; c++)
            s += g_Kpart[((size_t)bh * CH_ + c) * M_ + m];
        g_Ksum[(size_t)bh * M_ + m] = s;
    }
}

// ====== kernel 4: ctx ====================================================
__global__ __launch_bounds__(256) void k_ctx() {
    __shared__ float Qs[64][68];
    __shared__ float Ss[64][68];
    __shared__ float Kss[64];
    const int t = threadIdx.x;
    const int tr = t >> 4, tc = t & 15;
    const int bh = blockIdx.x;
    const int n0 = blockIdx.y * 64;

    float acc[4][4];
    float den[4];
#pragma unroll
    for (int i = 0; i < 4; i++) {
        den[i] = 0.0f;
#pragma unroll
        for (int j = 0; j < 4; j++) acc[i][j] = 0.0f;
    }

    for (int kt = 0; kt < 4; kt++) {
        const int k0 = kt * 64;
#pragma unroll
        for (int it = 0; it < 4; it++) {
            int lin = it * 256 + t;
            int r = lin >> 4, kq = lin & 15;
            float4 v = *(const float4*)(g_Qf + ((size_t)bh * N_ + n0 + r) * M_ + k0 + kq * 4);
            *(float4*)&Qs[r][kq * 4] = v;
        }
#pragma unroll
        for (int it = 0; it < 4; it++) {
            int lin = it * 256 + t;
            int kr = lin >> 4, dq = lin & 15;
            float4 v = *(const float4*)(g_S + ((size_t)bh * M_ + k0 + kr) * DK_ + dq * 4);
            *(float4*)&Ss[kr][dq * 4] = v;
        }
        if (t < 64) Kss[t] = g_Ksum[(size_t)bh * M_ + k0 + t];
        __syncthreads();
#pragma unroll 8
        for (int k = 0; k < 64; k++) {
            float kv = Kss[k];
            float a[4], bb[4];
#pragma unroll
            for (int i = 0; i < 4; i++) a[i] = Qs[tr + 16 * i][k];
#pragma unroll
            for (int j = 0; j < 4; j++) bb[j] = Ss[k][tc + 16 * j];
#pragma unroll
            for (int i = 0; i < 4; i++) {
                den[i] = fmaf(a[i], kv, den[i]);
#pragma unroll
                for (int j = 0; j < 4; j++) acc[i][j] = fmaf(a[i], bb[j], acc[i][j]);
            }
        }
        __syncthreads();
    }
    const int bI = bh >> 4, h = bh & 15;
#pragma unroll
    for (int i = 0; i < 4; i++) {
        const int n = n0 + tr + 16 * i;
        float vv = g_valid[bI * N_ + n];
        float dn = vv / (den[i] + 1e-6f);
#pragma unroll
        for (int j = 0; j < 4; j++)
            g_ctx[((size_t)bI * N_ + n) * D_ + h * DK_ + tc + 16 * j] = acc[i][j] * dn;
    }
}

// ========================= launch ========================================
extern "C" void kernel_launch(void* const* d_in, const int* in_sizes, int n_in,
                              void* d_out, int out_size) {
    (void)in_sizes; (void)n_in; (void)out_size;
    const float* x     = (const float*)d_in[0];
    const float* Wqkv  = (const float*)d_in[1];
    const float* bqkv  = (const float*)d_in[2];
    const float* Wout  = (const float*)d_in[3];
    const float* bout  = (const float*)d_in[4];
    const float* omega = (const float*)d_in[5];
    const void*  mask  = d_in[6];
    float* out = (float*)d_out;

    k_mask<<<1, 256>>>(mask);
    k_gemm_mma<<<dim3(24, 128), 256>>>(x, Wqkv, bqkv, nullptr, 0);
    k_phi<<<dim3(BH_, N_ / 64), 256>>>(omega, 0);
    k_phi<<<dim3(BH_, N_ / 64), 256>>>(omega, 1);
    k_spart<<<dim3(BH_, CH_), 256>>>();
    {
        const int tot = BH_ * M_ * (DK_ + 1);
        k_sreduce<<<(tot + 255) / 256, 256>>>();
    }
    k_ctx<<<dim3(BH_, N_ / 64), 256>>>();
    k_gemm_mma<<<dim3(8, 128), 256>>>(x, Wout, bout, out, 1);
}

// round 7
// speedup vs baseline: 1.3500x; 1.0224x over previous
#include <cuda_runtime.h>
#include <cstdint>
#include <math.h>

// FAVOR+ attention  B=4,N=4096,D=1024,H=16,dk=64,M=256
// R7: phi feature map rebuilt on mma.sync TF32 3x (was FFMA at 41% fma).
// Q/K phi merged into one launch (grid.z=2). GEMMs/spart/ctx = passing R6.

namespace {
constexpr int B_  = 4;
constexpr int N_  = 4096;
constexpr int D_  = 1024;
constexpr int H_  = 16;
constexpr int DK_ = 64;
constexpr int M_  = 256;
constexpr int BH_ = B_ * H_;
constexpr int CH_ = 16;
}

// -------- device scratch --------
__device__ float g_valid[B_ * N_];
__device__ float g_Q[BH_ * N_ * DK_];
__device__ float g_K[BH_ * N_ * DK_];
__device__ float g_V[BH_ * N_ * DK_];
__device__ float g_Qf[(size_t)BH_ * N_ * M_];
__device__ float g_Kf[(size_t)BH_ * N_ * M_];
__device__ float g_Spart[(size_t)BH_ * CH_ * M_ * DK_];
__device__ float g_Kpart[BH_ * CH_ * M_];
__device__ float g_S[BH_ * M_ * DK_];
__device__ float g_Ksum[BH_ * M_];
__device__ float g_ctx[(size_t)B_ * N_ * D_];

// ---- helpers ----
__device__ __forceinline__ uint32_t smem_u32(const void* p) {
    uint32_t a;
    asm("{ .reg .u64 t; cvta.to.shared.u64 t, %1; cvt.u32.u64 %0, t; }"
        : "=r"(a) : "l"(p));
    return a;
}
__device__ __forceinline__ void cp_async16(void* sdst, const void* gsrc) {
    asm volatile("cp.async.cg.shared.global [%0], [%1], 16;"
                 :: "r"(smem_u32(sdst)), "l"(gsrc) : "memory");
}
__device__ __forceinline__ void tf32_split(float f, uint32_t& h, uint32_t& l) {
    uint32_t hb;
    asm("cvt.rna.tf32.f32 %0, %1;" : "=r"(hb) : "f"(f));
    float lf = f - __uint_as_float(hb);
    uint32_t lb;
    asm("cvt.rna.tf32.f32 %0, %1;" : "=r"(lb) : "f"(lf));
    h = hb; l = lb;
}
__device__ __forceinline__ void mma_tf32(float* c, const uint32_t* a, const uint32_t* b) {
    asm volatile(
        "mma.sync.aligned.m16n8k8.row.col.f32.tf32.tf32.f32 "
        "{%0,%1,%2,%3}, {%4,%5,%6,%7}, {%8,%9}, {%0,%1,%2,%3};"
        : "+f"(c[0]), "+f"(c[1]), "+f"(c[2]), "+f"(c[3])
        : "r"(a[0]), "r"(a[1]), "r"(a[2]), "r"(a[3]), "r"(b[0]), "r"(b[1]));
}

// ============ mma.sync TF32 3x GEMM: C(128x128 tile) = A @ Bw^T ==========
__global__ __launch_bounds__(256) void k_gemm_mma(const float* __restrict__ A,
                                                  const float* __restrict__ Bw,
                                                  const float* __restrict__ bias,
                                                  float* __restrict__ Cp,
                                                  int mode) {
    __shared__ __align__(16) float As[2][128][20];
    __shared__ __align__(16) float Bs[2][128][20];
    const int t = threadIdx.x;
    const int lane = t & 31, wid = t >> 5;
    const int g = lane >> 2, tg = lane & 3;
    const int wm = wid >> 2, wn = wid & 3;
    const int rb = blockIdx.y * 128, cb = blockIdx.x * 128;
    constexpr int K = 1024;
    constexpr int NSLAB = K / 16;
    const float* Ap = (mode == 1) ? (const float*)g_ctx : A;

    float acc[4][4][4];
#pragma unroll
    for (int i = 0; i < 4; i++)
#pragma unroll
        for (int j = 0; j < 4; j++)
#pragma unroll
            for (int e = 0; e < 4; e++) acc[i][j][e] = 0.0f;

    {
#pragma unroll
        for (int it = 0; it < 2; it++) {
            int f = it * 256 + t;
            int r = f >> 2, q = f & 3;
            cp_async16(&As[0][r][q * 4], Ap + (size_t)(rb + r) * K + q * 4);
            cp_async16(&Bs[0][r][q * 4], Bw + (size_t)(cb + r) * K + q * 4);
        }
        asm volatile("cp.async.commit_group;" ::: "memory");
    }

    for (int sl = 0; sl < NSLAB; sl++) {
        const int st = sl & 1;
        if (sl + 1 < NSLAB) {
            const int kt = (sl + 1) * 16;
            const int ns = st ^ 1;
#pragma unroll
            for (int it = 0; it < 2; it++) {
                int f = it * 256 + t;
                int r = f >> 2, q = f & 3;
                cp_async16(&As[ns][r][q * 4], Ap + (size_t)(rb + r) * K + kt + q * 4);
                cp_async16(&Bs[ns][r][q * 4], Bw + (size_t)(cb + r) * K + kt + q * 4);
            }
            asm volatile("cp.async.commit_group;" ::: "memory");
            asm volatile("cp.async.wait_group 1;" ::: "memory");
        } else {
            asm volatile("cp.async.wait_group 0;" ::: "memory");
        }
        __syncthreads();

#pragma unroll
        for (int ks = 0; ks < 2; ks++) {
            const int k0 = ks * 8;
            uint32_t ah[4][4], al[4][4], bh[4][2], bl[4][2];
#pragma unroll
            for (int i = 0; i < 4; i++) {
                const int m0 = wm * 64 + i * 16;
                tf32_split(As[st][m0 + g    ][k0 + tg    ], ah[i][0], al[i][0]);
                tf32_split(As[st][m0 + g + 8][k0 + tg    ], ah[i][1], al[i][1]);
                tf32_split(As[st][m0 + g    ][k0 + tg + 4], ah[i][2], al[i][2]);
                tf32_split(As[st][m0 + g + 8][k0 + tg + 4], ah[i][3], al[i][3]);
            }
#pragma unroll
            for (int j = 0; j < 4; j++) {
                const int n0 = wn * 32 + j * 8;
                tf32_split(Bs[st][n0 + g][k0 + tg    ], bh[j][0], bl[j][0]);
                tf32_split(Bs[st][n0 + g][k0 + tg + 4], bh[j][1], bl[j][1]);
            }
#pragma unroll
            for (int i = 0; i < 4; i++)
#pragma unroll
                for (int j = 0; j < 4; j++) mma_tf32(acc[i][j], ah[i], bh[j]);
#pragma unroll
            for (int i = 0; i < 4; i++)
#pragma unroll
                for (int j = 0; j < 4; j++) mma_tf32(acc[i][j], ah[i], bl[j]);
#pragma unroll
            for (int i = 0; i < 4; i++)
#pragma unroll
                for (int j = 0; j < 4; j++) mma_tf32(acc[i][j], al[i], bh[j]);
        }
        __syncthreads();
    }

#pragma unroll
    for (int i = 0; i < 4; i++) {
        const int r0 = rb + wm * 64 + i * 16 + g;
#pragma unroll
        for (int j = 0; j < 4; j++) {
            const int c = cb + wn * 32 + j * 8 + tg * 2;
            const float b0 = bias[c], b1 = bias[c + 1];
            if (mode == 1) {
                *(float2*)(Cp + (size_t)r0 * 1024 + c) =
                    make_float2(acc[i][j][0] + b0, acc[i][j][1] + b1);
                *(float2*)(Cp + (size_t)(r0 + 8) * 1024 + c) =
                    make_float2(acc[i][j][2] + b0, acc[i][j][3] + b1);
            } else {
                const int which = c >> 10;
                const int hh = (c & 1023) >> 6;
                const int dk = c & 63;
#pragma unroll
                for (int half = 0; half < 2; half++) {
                    const int r = r0 + half * 8;
                    const float vv = g_valid[r];
                    const float v0 = acc[i][j][half * 2 + 0] + b0;
                    const float v1 = acc[i][j][half * 2 + 1] + b1;
                    size_t off = ((((size_t)(r >> 12)) * H_ + hh) * N_ + (r & 4095)) * DK_ + dk;
                    if (which == 0)
                        *(float2*)(g_Q + off) = make_float2(v0 * vv, v1 * vv);
                    else if (which == 1)
                        *(float2*)(g_K + off) = make_float2(v0, v1);
                    else
                        *(float2*)(g_V + off) = make_float2(v0 * vv, v1 * vv);
                }
            }
        }
    }
}

// ===================== kernel 0: mask -> valid ==========================
__global__ void k_mask(const void* __restrict__ mask) {
    __shared__ int sF, sOdd;
    const int t = threadIdx.x;
    if (t == 0) { sF = 0; sOdd = 0; }
    __syncthreads();
    const unsigned* w = (const unsigned*)mask;
    for (int i = t; i < 4096; i += 256) {
        unsigned v = w[i];
        if (v == 0x3F800000u) sF = 1;
        else if (v != 0u && v != 1u) sOdd = 1;
    }
    __syncthreads();
    if (sF) {
        const float* m = (const float*)mask;
        for (int i = t; i < B_ * N_; i += 256)
            g_valid[i] = (m[i] != 0.0f) ? 0.0f : 1.0f;
    } else if (sOdd) {
        const unsigned char* m = (const unsigned char*)mask;
        for (int i = t; i < B_ * N_; i += 256)
            g_valid[i] = m[i] ? 0.0f : 1.0f;
    } else {
        const int* m = (const int*)mask;
        for (int i = t; i < B_ * N_; i += 256)
            g_valid[i] = m[i] ? 0.0f : 1.0f;
    }
}

// ======= kernel 2: phi via mma.sync TF32 3x (Q: z=0, K: z=1) ============
// Per block: 64 n-rows, all M=256 features. proj = T(64x64) @ omega^T.
// Warp grid 2(m)x4(n): warp tile 32 rows x 64 features.
__global__ __launch_bounds__(256) void k_phi_mma(const float* __restrict__ omega) {
    __shared__ __align__(16) float pool[11520];  // Ts[64][36]@0, Om[256][36]@2304
    __shared__ float s_max[4][64];
    __shared__ float s_sq[64];
    float* Ts  = pool;           // stride 36
    float* Om  = pool + 2304;    // stride 36
    float* Stg = pool + 2304;    // staging alias [32][264]

    const int t = threadIdx.x, lane = t & 31, wid = t >> 5;
    const int g = lane >> 2, tg = lane & 3;
    const int wm = wid >> 2, wn = wid & 3;
    const int isK = blockIdx.z;
    const int bh = blockIdx.x;
    const int n0 = blockIdx.y * 64;
    const int h  = bh & (H_ - 1);
    const float* In  = isK ? g_K  : g_Q;
    float*       Out = isK ? g_Kf : g_Qf;

    float acc[2][8][4];
#pragma unroll
    for (int mi = 0; mi < 2; mi++)
#pragma unroll
        for (int nj = 0; nj < 8; nj++)
#pragma unroll
            for (int e = 0; e < 4; e++) acc[mi][nj][e] = 0.0f;

    for (int kp = 0; kp < 2; kp++) {
        const int k0g = kp * 32;
#pragma unroll
        for (int it = 0; it < 2; it++) {      // T tile 64x32
            int f = it * 256 + t;
            int r = f >> 3, q = f & 7;
            float4 v = *(const float4*)(In + ((size_t)bh * N_ + n0 + r) * DK_ + k0g + q * 4);
            *(float4*)(Ts + r * 36 + q * 4) = v;
        }
#pragma unroll
        for (int it = 0; it < 8; it++) {      // omega 256x32
            int f = it * 256 + t;
            int r = f >> 3, q = f & 7;
            float4 v = *(const float4*)(omega + ((size_t)h * M_ + r) * DK_ + k0g + q * 4);
            *(float4*)(Om + r * 36 + q * 4) = v;
        }
        __syncthreads();
        if (t < 64) {                          // ||t||^2 partial
            float s = 0.0f;
#pragma unroll
            for (int k = 0; k < 32; k++) { float q = Ts[t * 36 + k]; s += q * q; }
            if (kp == 0) s_sq[t] = s; else s_sq[t] += s;
        }
#pragma unroll
        for (int ks = 0; ks < 4; ks++) {
            const int k0 = ks * 8;
            uint32_t ah[2][4], al[2][4], obh[8][2], obl[8][2];
#pragma unroll
            for (int mi = 0; mi < 2; mi++) {
                const int m0 = wm * 32 + mi * 16;
                tf32_split(Ts[(m0 + g    ) * 36 + k0 + tg    ], ah[mi][0], al[mi][0]);
                tf32_split(Ts[(m0 + g + 8) * 36 + k0 + tg    ], ah[mi][1], al[mi][1]);
                tf32_split(Ts[(m0 + g    ) * 36 + k0 + tg + 4], ah[mi][2], al[mi][2]);
                tf32_split(Ts[(m0 + g + 8) * 36 + k0 + tg + 4], ah[mi][3], al[mi][3]);
            }
#pragma unroll
            for (int nj = 0; nj < 8; nj++) {
                const int nc = wn * 64 + nj * 8;
                tf32_split(Om[(nc + g) * 36 + k0 + tg    ], obh[nj][0], obl[nj][0]);
                tf32_split(Om[(nc + g) * 36 + k0 + tg + 4], obh[nj][1], obl[nj][1]);
            }
#pragma unroll
            for (int mi = 0; mi < 2; mi++)
#pragma unroll
                for (int nj = 0; nj < 8; nj++) mma_tf32(acc[mi][nj], ah[mi], obh[nj]);
#pragma unroll
            for (int mi = 0; mi < 2; mi++)
#pragma unroll
                for (int nj = 0; nj < 8; nj++) mma_tf32(acc[mi][nj], ah[mi], obl[nj]);
#pragma unroll
            for (int mi = 0; mi < 2; mi++)
#pragma unroll
                for (int nj = 0; nj < 8; nj++) mma_tf32(acc[mi][nj], al[mi], obh[nj]);
        }
        __syncthreads();
    }

    // row-max partials: thread covers rows (wm*32+mi*16+g) and (+8)
#pragma unroll
    for (int mi = 0; mi < 2; mi++) {
#pragma unroll
        for (int half = 0; half < 2; half++) {
            float m = acc[mi][0][half * 2];
#pragma unroll
            for (int nj = 0; nj < 8; nj++) {
                m = fmaxf(m, acc[mi][nj][half * 2]);
                m = fmaxf(m, acc[mi][nj][half * 2 + 1]);
            }
            m = fmaxf(m, __shfl_xor_sync(0xffffffffu, m, 1));
            m = fmaxf(m, __shfl_xor_sync(0xffffffffu, m, 2));
            if (tg == 0) s_max[wn][wm * 32 + mi * 16 + half * 8 + g] = m;
        }
    }
    __syncthreads();

    const float invs = rsqrtf(256.0f + 1e-6f);
    const int bI = bh >> 4;
    for (int hr = 0; hr < 2; hr++) {
        if (hr) __syncthreads();
        if (wm == hr) {
#pragma unroll
            for (int mi = 0; mi < 2; mi++)
#pragma unroll
            for (int half = 0; half < 2; half++) {
                const int rloc = mi * 16 + half * 8 + g;
                const int rg = hr * 32 + rloc;
                float rm = fmaxf(fmaxf(s_max[0][rg], s_max[1][rg]),
                                 fmaxf(s_max[2][rg], s_max[3][rg]));
                float e = -rm - 0.5f * s_sq[rg];
                float sc = invs;
                if (isK) sc *= g_valid[bI * N_ + n0 + rg];
#pragma unroll
                for (int nj = 0; nj < 8; nj++) {
                    const int col = wn * 64 + nj * 8 + tg * 2;
                    *(float2*)(Stg + rloc * 264 + col) = make_float2(
                        expf(acc[mi][nj][half * 2    ] + e) * sc,
                        expf(acc[mi][nj][half * 2 + 1] + e) * sc);
                }
            }
        }
        __syncthreads();
#pragma unroll
        for (int it = 0; it < 8; it++) {
            int f = it * 256 + t;
            int r = f >> 6, q = f & 63;
            float4 v = *(float4*)(Stg + r * 264 + q * 4);
            *(float4*)(Out + ((size_t)bh * N_ + n0 + hr * 32 + r) * M_ + q * 4) = v;
        }
    }
}

// ====== kernel 3: S partials ============================================
__global__ __launch_bounds__(256) void k_spart() {
    __shared__ float Ks[32][260];
    __shared__ float Vs[32][68];
    const int t = threadIdx.x;
    const int tmg = t >> 3, tdg = t & 7;
    const int bh = blockIdx.x, ch = blockIdx.y;

    float acc[8][8];
    float ks[8];
#pragma unroll
    for (int i = 0; i < 8; i++) {
        ks[i] = 0.0f;
#pragma unroll
        for (int j = 0; j < 8; j++) acc[i][j] = 0.0f;
    }

    for (int tile = 0; tile < 8; tile++) {
        const int nb = ch * 256 + tile * 32;
#pragma unroll
        for (int it = 0; it < 8; it++) {
            int lin = it * 256 + t;
            int r = lin >> 6, mq = lin & 63;
            float4 v = *(const float4*)(g_Kf + ((size_t)bh * N_ + nb + r) * M_ + mq * 4);
            *(float4*)&Ks[r][mq * 4] = v;
        }
#pragma unroll
        for (int it = 0; it < 2; it++) {
            int lin = it * 256 + t;
            int r = lin >> 4, dq = lin & 15;
            float4 v = *(const float4*)(g_V + ((size_t)bh * N_ + nb + r) * DK_ + dq * 4);
            *(float4*)&Vs[r][dq * 4] = v;
        }
        __syncthreads();
#pragma unroll 4
        for (int n = 0; n < 32; n++) {
            float a[8], bb[8];
#pragma unroll
            for (int i = 0; i < 8; i++) a[i] = Ks[n][tmg * 8 + i];
#pragma unroll
            for (int j = 0; j < 8; j++) bb[j] = Vs[n][tdg * 8 + j];
#pragma unroll
            for (int i = 0; i < 8; i++)
#pragma unroll
                for (int j = 0; j < 8; j++) acc[i][j] = fmaf(a[i], bb[j], acc[i][j]);
            if (tdg == 0) {
#pragma unroll
                for (int i = 0; i < 8; i++) ks[i] += a[i];
            }
        }
        __syncthreads();
    }
#pragma unroll
    for (int i = 0; i < 8; i++)
#pragma unroll
        for (int j = 0; j < 8; j++)
            g_Spart[(((size_t)bh * CH_ + ch) * M_ + tmg * 8 + i) * DK_ + tdg * 8 + j] = acc[i][j];
    if (tdg == 0) {
#pragma unroll
        for (int i = 0; i < 8; i++)
            g_Kpart[((size_t)bh * CH_ + ch) * M_ + tmg * 8 + i] = ks[i];
    }
}

// ============ kernel 3b: deterministic chunk reduction ===================
__global__ void k_sreduce() {
    const int tot = BH_ * M_ * (DK_ + 1);
    int idx = blockIdx.x * 256 + threadIdx.x;
    if (idx >= tot) return;
    int bh  = idx / (M_ * (DK_ + 1));
    int rem = idx % (M_ * (DK_ + 1));
    int m = rem / (DK_ + 1);
    int d = rem % (DK_ + 1);
    if (d < DK_) {
        float s = 0.0f;
#pragma unroll
        for (int c = 0; c < CH_; c++)
            s += g_Spart[(((size_t)bh * CH_ + c) * M_ + m) * DK_ + d];
        g_S[((size_t)bh * M_ + m) * DK_ + d] = s;
    } else {
        float s = 0.0f;
#pragma unroll
        for (int c = 0; c < CH_; c++)
            s += g_Kpart[((size_t)bh * CH_ + c) * M_ + m];
        g_Ksum[(size_t)bh * M_ + m] = s;
    }
}

// ====== kernel 4: ctx ====================================================
__global__ __launch_bounds__(256) void k_ctx() {
    __shared__ float Qs[64][68];
    __shared__ float Ss[64][68];
    __shared__ float Kss[64];
    const int t = threadIdx.x;
    const int tr = t >> 4, tc = t & 15;
    const int bh = blockIdx.x;
    const int n0 = blockIdx.y * 64;

    float acc[4][4];
    float den[4];
#pragma unroll
    for (int i = 0; i < 4; i++) {
        den[i] = 0.0f;
#pragma unroll
        for (int j = 0; j < 4; j++) acc[i][j] = 0.0f;
    }

    for (int kt = 0; kt < 4; kt++) {
        const int k0 = kt * 64;
#pragma unroll
        for (int it = 0; it < 4; it++) {
            int lin = it * 256 + t;
            int r = lin >> 4, kq = lin & 15;
            float4 v = *(const float4*)(g_Qf + ((size_t)bh * N_ + n0 + r) * M_ + k0 + kq * 4);
            *(float4*)&Qs[r][kq * 4] = v;
        }
#pragma unroll
        for (int it = 0; it < 4; it++) {
            int lin = it * 256 + t;
            int kr = lin >> 4, dq = lin & 15;
            float4 v = *(const float4*)(g_S + ((size_t)bh * M_ + k0 + kr) * DK_ + dq * 4);
            *(float4*)&Ss[kr][dq * 4] = v;
        }
        if (t < 64) Kss[t] = g_Ksum[(size_t)bh * M_ + k0 + t];
        __syncthreads();
#pragma unroll 8
        for (int k = 0; k < 64; k++) {
            float kv = Kss[k];
            float a[4], bb[4];
#pragma unroll
            for (int i = 0; i < 4; i++) a[i] = Qs[tr + 16 * i][k];
#pragma unroll
            for (int j = 0; j < 4; j++) bb[j] = Ss[k][tc + 16 * j];
#pragma unroll
            for (int i = 0; i < 4; i++) {
                den[i] = fmaf(a[i], kv, den[i]);
#pragma unroll
                for (int j = 0; j < 4; j++) acc[i][j] = fmaf(a[i], bb[j], acc[i][j]);
            }
        }
        __syncthreads();
    }
    const int bI = bh >> 4, h = bh & 15;
#pragma unroll
    for (int i = 0; i < 4; i++) {
        const int n = n0 + tr + 16 * i;
        float vv = g_valid[bI * N_ + n];
        float dn = vv / (den[i] + 1e-6f);
#pragma unroll
        for (int j = 0; j < 4; j++)
            g_ctx[((size_t)bI * N_ + n) * D_ + h * DK_ + tc + 16 * j] = acc[i][j] * dn;
    }
}

// ========================= launch ========================================
extern "C" void kernel_launch(void* const* d_in, const int* in_sizes, int n_in,
                              void* d_out, int out_size) {
    (void)in_sizes; (void)n_in; (void)out_size;
    const float* x     = (const float*)d_in[0];
    const float* Wqkv  = (const float*)d_in[1];
    const float* bqkv  = (const float*)d_in[2];
    const float* Wout  = (const float*)d_in[3];
    const float* bout  = (const float*)d_in[4];
    const float* omega = (const float*)d_in[5];
    const void*  mask  = d_in[6];
    float* out = (float*)d_out;

    k_mask<<<1, 256>>>(mask);
    k_gemm_mma<<<dim3(24, 128), 256>>>(x, Wqkv, bqkv, nullptr, 0);
    k_phi_mma<<<dim3(BH_, N_ / 64, 2), 256>>>(omega);
    k_spart<<<dim3(BH_, CH_), 256>>>();
    {
        const int tot = BH_ * M_ * (DK_ + 1);
        k_sreduce<<<(tot + 255) / 256, 256>>>();
    }
    k_ctx<<<dim3(BH_, N_ / 64), 256>>>();
    k_gemm_mma<<<dim3(8, 128), 256>>>(x, Wout, bout, out, 1);
}

// round 9
// speedup vs baseline: 1.4028x; 1.0391x over previous
#include <cuda_runtime.h>
#include <cstdint>
#include <math.h>

// FAVOR+ attention  B=4,N=4096,D=1024,H=16,dk=64,M=256
// R9 = R8 resubmission (R8 never ran: brokered-container infra failure,
// same flake as R0/R2/R4; R4's unchanged resubmit in R5 ran clean).
// FUSION — Qf/Kf never materialized (saves ~1.07GB DRAM round-trip):
//   kernel A: phi(K) + S/Ksum partial accumulation (tf32-3x mma) + sreduce
//   kernel B: phi(Q) + ctx (tf32-3x mma vs S slabs) + denom + mask
// QKV/OUT GEMMs = passing R6/R7 code.

namespace {
constexpr int B_  = 4;
constexpr int N_  = 4096;
constexpr int D_  = 1024;
constexpr int H_  = 16;
constexpr int DK_ = 64;
constexpr int M_  = 256;
constexpr int BH_ = B_ * H_;
constexpr int CH_ = 16;
}

// -------- device scratch --------
__device__ float g_valid[B_ * N_];
__device__ float g_Q[BH_ * N_ * DK_];
__device__ float g_K[BH_ * N_ * DK_];
__device__ float g_V[BH_ * N_ * DK_];
__device__ float g_Spart[(size_t)BH_ * CH_ * M_ * DK_];
__device__ float g_Kpart[BH_ * CH_ * M_];
__device__ float g_S[BH_ * M_ * DK_];
__device__ float g_Ksum[BH_ * M_];
__device__ float g_ctx[(size_t)B_ * N_ * D_];

// ---- helpers ----
__device__ __forceinline__ uint32_t smem_u32(const void* p) {
    uint32_t a;
    asm("{ .reg .u64 t; cvta.to.shared.u64 t, %1; cvt.u32.u64 %0, t; }"
        : "=r"(a) : "l"(p));
    return a;
}
__device__ __forceinline__ void cp_async16(void* sdst, const void* gsrc) {
    asm volatile("cp.async.cg.shared.global [%0], [%1], 16;"
                 :: "r"(smem_u32(sdst)), "l"(gsrc) : "memory");
}
__device__ __forceinline__ void tf32_split(float f, uint32_t& h, uint32_t& l) {
    uint32_t hb;
    asm("cvt.rna.tf32.f32 %0, %1;" : "=r"(hb) : "f"(f));
    float lf = f - __uint_as_float(hb);
    uint32_t lb;
    asm("cvt.rna.tf32.f32 %0, %1;" : "=r"(lb) : "f"(lf));
    h = hb; l = lb;
}
__device__ __forceinline__ void mma_tf32(float* c, const uint32_t* a, const uint32_t* b) {
    asm volatile(
        "mma.sync.aligned.m16n8k8.row.col.f32.tf32.tf32.f32 "
        "{%0,%1,%2,%3}, {%4,%5,%6,%7}, {%8,%9}, {%0,%1,%2,%3};"
        : "+f"(c[0]), "+f"(c[1]), "+f"(c[2]), "+f"(c[3])
        : "r"(a[0]), "r"(a[1]), "r"(a[2]), "r"(a[3]), "r"(b[0]), "r"(b[1]));
}

// ============ mma.sync TF32 3x GEMM: C(128x128 tile) = A @ Bw^T ==========
__global__ __launch_bounds__(256) void k_gemm_mma(const float* __restrict__ A,
                                                  const float* __restrict__ Bw,
                                                  const float* __restrict__ bias,
                                                  float* __restrict__ Cp,
                                                  int mode) {
    __shared__ __align__(16) float As[2][128][20];
    __shared__ __align__(16) float Bs[2][128][20];
    const int t = threadIdx.x;
    const int lane = t & 31, wid = t >> 5;
    const int g = lane >> 2, tg = lane & 3;
    const int wm = wid >> 2, wn = wid & 3;
    const int rb = blockIdx.y * 128, cb = blockIdx.x * 128;
    constexpr int K = 1024;
    constexpr int NSLAB = K / 16;
    const float* Ap = (mode == 1) ? (const float*)g_ctx : A;

    float acc[4][4][4];
#pragma unroll
    for (int i = 0; i < 4; i++)
#pragma unroll
        for (int j = 0; j < 4; j++)
#pragma unroll
            for (int e = 0; e < 4; e++) acc[i][j][e] = 0.0f;

    {
#pragma unroll
        for (int it = 0; it < 2; it++) {
            int f = it * 256 + t;
            int r = f >> 2, q = f & 3;
            cp_async16(&As[0][r][q * 4], Ap + (size_t)(rb + r) * K + q * 4);
            cp_async16(&Bs[0][r][q * 4], Bw + (size_t)(cb + r) * K + q * 4);
        }
        asm volatile("cp.async.commit_group;" ::: "memory");
    }

    for (int sl = 0; sl < NSLAB; sl++) {
        const int st = sl & 1;
        if (sl + 1 < NSLAB) {
            const int kt = (sl + 1) * 16;
            const int ns = st ^ 1;
#pragma unroll
            for (int it = 0; it < 2; it++) {
                int f = it * 256 + t;
                int r = f >> 2, q = f & 3;
                cp_async16(&As[ns][r][q * 4], Ap + (size_t)(rb + r) * K + kt + q * 4);
                cp_async16(&Bs[ns][r][q * 4], Bw + (size_t)(cb + r) * K + kt + q * 4);
            }
            asm volatile("cp.async.commit_group;" ::: "memory");
            asm volatile("cp.async.wait_group 1;" ::: "memory");
        } else {
            asm volatile("cp.async.wait_group 0;" ::: "memory");
        }
        __syncthreads();

#pragma unroll
        for (int ks = 0; ks < 2; ks++) {
            const int k0 = ks * 8;
            uint32_t ah[4][4], al[4][4], bh[4][2], bl[4][2];
#pragma unroll
            for (int i = 0; i < 4; i++) {
                const int m0 = wm * 64 + i * 16;
                tf32_split(As[st][m0 + g    ][k0 + tg    ], ah[i][0], al[i][0]);
                tf32_split(As[st][m0 + g + 8][k0 + tg    ], ah[i][1], al[i][1]);
                tf32_split(As[st][m0 + g    ][k0 + tg + 4], ah[i][2], al[i][2]);
                tf32_split(As[st][m0 + g + 8][k0 + tg + 4], ah[i][3], al[i][3]);
            }
#pragma unroll
            for (int j = 0; j < 4; j++) {
                const int n0 = wn * 32 + j * 8;
                tf32_split(Bs[st][n0 + g][k0 + tg    ], bh[j][0], bl[j][0]);
                tf32_split(Bs[st][n0 + g][k0 + tg + 4], bh[j][1], bl[j][1]);
            }
#pragma unroll
            for (int i = 0; i < 4; i++)
#pragma unroll
                for (int j = 0; j < 4; j++) mma_tf32(acc[i][j], ah[i], bh[j]);
#pragma unroll
            for (int i = 0; i < 4; i++)
#pragma unroll
                for (int j = 0; j < 4; j++) mma_tf32(acc[i][j], ah[i], bl[j]);
#pragma unroll
            for (int i = 0; i < 4; i++)
#pragma unroll
                for (int j = 0; j < 4; j++) mma_tf32(acc[i][j], al[i], bh[j]);
        }
        __syncthreads();
    }

#pragma unroll
    for (int i = 0; i < 4; i++) {
        const int r0 = rb + wm * 64 + i * 16 + g;
#pragma unroll
        for (int j = 0; j < 4; j++) {
            const int c = cb + wn * 32 + j * 8 + tg * 2;
            const float b0 = bias[c], b1 = bias[c + 1];
            if (mode == 1) {
                *(float2*)(Cp + (size_t)r0 * 1024 + c) =
                    make_float2(acc[i][j][0] + b0, acc[i][j][1] + b1);
                *(float2*)(Cp + (size_t)(r0 + 8) * 1024 + c) =
                    make_float2(acc[i][j][2] + b0, acc[i][j][3] + b1);
            } else {
                const int which = c >> 10;
                const int hh = (c & 1023) >> 6;
                const int dk = c & 63;
#pragma unroll
                for (int half = 0; half < 2; half++) {
                    const int r = r0 + half * 8;
                    const float vv = g_valid[r];
                    const float v0 = acc[i][j][half * 2 + 0] + b0;
                    const float v1 = acc[i][j][half * 2 + 1] + b1;
                    size_t off = ((((size_t)(r >> 12)) * H_ + hh) * N_ + (r & 4095)) * DK_ + dk;
                    if (which == 0)
                        *(float2*)(g_Q + off) = make_float2(v0 * vv, v1 * vv);
                    else if (which == 1)
                        *(float2*)(g_K + off) = make_float2(v0, v1);
                    else
                        *(float2*)(g_V + off) = make_float2(v0 * vv, v1 * vv);
                }
            }
        }
    }
}

// ===================== kernel 0: mask -> valid ==========================
__global__ void k_mask(const void* __restrict__ mask) {
    __shared__ int sF, sOdd;
    const int t = threadIdx.x;
    if (t == 0) { sF = 0; sOdd = 0; }
    __syncthreads();
    const unsigned* w = (const unsigned*)mask;
    for (int i = t; i < 4096; i += 256) {
        unsigned v = w[i];
        if (v == 0x3F800000u) sF = 1;
        else if (v != 0u && v != 1u) sOdd = 1;
    }
    __syncthreads();
    if (sF) {
        const float* m = (const float*)mask;
        for (int i = t; i < B_ * N_; i += 256)
            g_valid[i] = (m[i] != 0.0f) ? 0.0f : 1.0f;
    } else if (sOdd) {
        const unsigned char* m = (const unsigned char*)mask;
        for (int i = t; i < B_ * N_; i += 256)
            g_valid[i] = m[i] ? 0.0f : 1.0f;
    } else {
        const int* m = (const int*)mask;
        for (int i = t; i < B_ * N_; i += 256)
            g_valid[i] = m[i] ? 0.0f : 1.0f;
    }
}

// ====== kernel A: phi(K) fused with S/Ksum partial accumulation =========
// grid (BH, CH). Block: 256 rows (4 tiles of 64). Per tile: phi-mma to
// staging smem (32-row halves), then S += Kf^T V via tf32-3x mma.
__global__ __launch_bounds__(256) void k_phik_spart(const float* __restrict__ omega) {
    __shared__ __align__(16) float pool[11520];   // 46.1 KB
    __shared__ float s_max[4][64];
    __shared__ float s_sq[64];
    float* Ts  = pool;            // [64][36]
    float* Om  = pool + 2304;     // [256][36]
    float* Stg = pool;            // [32][264] alias (phi phase done)
    float* Vs  = pool + 8448;     // [32][72]

    const int t = threadIdx.x, lane = t & 31, wid = t >> 5;
    const int g = lane >> 2, tg = lane & 3;
    const int wm = wid >> 2, wn = wid & 3;       // phi warp grid 2m x 4n
    const int wmA = wid >> 1, wnA = wid & 1;     // spart warp grid 4m x 2n
    const int bh = blockIdx.x, ch = blockIdx.y;
    const int h = bh & (H_ - 1), bI = bh >> 4;
    const float invs = rsqrtf(256.0f + 1e-6f);

    float acc2[4][4][4];                          // S[256][64] block acc
#pragma unroll
    for (int i = 0; i < 4; i++)
#pragma unroll
        for (int j = 0; j < 4; j++)
#pragma unroll
            for (int e = 0; e < 4; e++) acc2[i][j][e] = 0.0f;
    float ksacc = 0.0f;                           // Ksum[feat t]

    for (int tile = 0; tile < 4; tile++) {
        const int n0 = ch * 256 + tile * 64;
        float acc[2][8][4];
#pragma unroll
        for (int mi = 0; mi < 2; mi++)
#pragma unroll
            for (int nj = 0; nj < 8; nj++)
#pragma unroll
                for (int e = 0; e < 4; e++) acc[mi][nj][e] = 0.0f;

        // ---- phi(K): proj = T(64x64) @ omega^T, tf32-3x
        for (int kp = 0; kp < 2; kp++) {
            const int k0g = kp * 32;
            __syncthreads();                      // pool reuse guard
#pragma unroll
            for (int it = 0; it < 2; it++) {
                int f = it * 256 + t;
                int r = f >> 3, q = f & 7;
                float4 v = *(const float4*)(g_K + ((size_t)bh * N_ + n0 + r) * DK_ + k0g + q * 4);
                *(float4*)(Ts + r * 36 + q * 4) = v;
            }
#pragma unroll
            for (int it = 0; it < 8; it++) {
                int f = it * 256 + t;
                int r = f >> 3, q = f & 7;
                float4 v = *(const float4*)(omega + ((size_t)h * M_ + r) * DK_ + k0g + q * 4);
                *(float4*)(Om + r * 36 + q * 4) = v;
            }
            __syncthreads();
            if (t < 64) {
                float ssum = 0.0f;
#pragma unroll
                for (int k = 0; k < 32; k++) { float q = Ts[t * 36 + k]; ssum += q * q; }
                if (kp == 0) s_sq[t] = ssum; else s_sq[t] += ssum;
            }
#pragma unroll
            for (int ks = 0; ks < 4; ks++) {
                const int k0 = ks * 8;
                uint32_t ah[2][4], al[2][4], obh[8][2], obl[8][2];
#pragma unroll
                for (int mi = 0; mi < 2; mi++) {
                    const int m0 = wm * 32 + mi * 16;
                    tf32_split(Ts[(m0 + g    ) * 36 + k0 + tg    ], ah[mi][0], al[mi][0]);
                    tf32_split(Ts[(m0 + g + 8) * 36 + k0 + tg    ], ah[mi][1], al[mi][1]);
                    tf32_split(Ts[(m0 + g    ) * 36 + k0 + tg + 4], ah[mi][2], al[mi][2]);
                    tf32_split(Ts[(m0 + g + 8) * 36 + k0 + tg + 4], ah[mi][3], al[mi][3]);
                }
#pragma unroll
                for (int nj = 0; nj < 8; nj++) {
                    const int nc = wn * 64 + nj * 8;
                    tf32_split(Om[(nc + g) * 36 + k0 + tg    ], obh[nj][0], obl[nj][0]);
                    tf32_split(Om[(nc + g) * 36 + k0 + tg + 4], obh[nj][1], obl[nj][1]);
                }
#pragma unroll
                for (int mi = 0; mi < 2; mi++)
#pragma unroll
                    for (int nj = 0; nj < 8; nj++) mma_tf32(acc[mi][nj], ah[mi], obh[nj]);
#pragma unroll
                for (int mi = 0; mi < 2; mi++)
#pragma unroll
                    for (int nj = 0; nj < 8; nj++) mma_tf32(acc[mi][nj], ah[mi], obl[nj]);
#pragma unroll
                for (int mi = 0; mi < 2; mi++)
#pragma unroll
                    for (int nj = 0; nj < 8; nj++) mma_tf32(acc[mi][nj], al[mi], obh[nj]);
            }
        }
        // ---- row-max partials
#pragma unroll
        for (int mi = 0; mi < 2; mi++) {
#pragma unroll
            for (int half = 0; half < 2; half++) {
                float m = acc[mi][0][half * 2];
#pragma unroll
                for (int nj = 0; nj < 8; nj++) {
                    m = fmaxf(m, acc[mi][nj][half * 2]);
                    m = fmaxf(m, acc[mi][nj][half * 2 + 1]);
                }
                m = fmaxf(m, __shfl_xor_sync(0xffffffffu, m, 1));
                m = fmaxf(m, __shfl_xor_sync(0xffffffffu, m, 2));
                if (tg == 0) s_max[wn][wm * 32 + mi * 16 + half * 8 + g] = m;
            }
        }
        __syncthreads();

        // ---- per 32-row half: stage Kf, accumulate Ksum + S
        for (int hr = 0; hr < 2; hr++) {
            if (wm == hr) {
#pragma unroll
                for (int mi = 0; mi < 2; mi++)
#pragma unroll
                for (int half = 0; half < 2; half++) {
                    const int rloc = mi * 16 + half * 8 + g;
                    const int rg = hr * 32 + rloc;
                    float rm = fmaxf(fmaxf(s_max[0][rg], s_max[1][rg]),
                                     fmaxf(s_max[2][rg], s_max[3][rg]));
                    float e = -rm - 0.5f * s_sq[rg];
                    float sc = invs * g_valid[bI * N_ + n0 + rg];
#pragma unroll
                    for (int nj = 0; nj < 8; nj++) {
                        const int col = wn * 64 + nj * 8 + tg * 2;
                        *(float2*)(Stg + rloc * 264 + col) = make_float2(
                            expf(acc[mi][nj][half * 2    ] + e) * sc,
                            expf(acc[mi][nj][half * 2 + 1] + e) * sc);
                    }
                }
            }
#pragma unroll
            for (int it = 0; it < 2; it++) {      // V chunk 32x64
                int f = it * 256 + t;
                int r = f >> 4, dq = f & 15;
                float4 v = *(const float4*)(g_V + ((size_t)bh * N_ + n0 + hr * 32 + r) * DK_ + dq * 4);
                *(float4*)(Vs + r * 72 + dq * 4) = v;
            }
            __syncthreads();
            // Ksum: thread t owns feature t
#pragma unroll 8
            for (int r = 0; r < 32; r++) ksacc += Stg[r * 264 + t];
            // S += Kf^T V  (A = Stg transposed, B = V)
#pragma unroll
            for (int ks = 0; ks < 4; ks++) {
                const int k0 = ks * 8;
                uint32_t ah[4][4], al[4][4], bhf[4][2], blf[4][2];
#pragma unroll
                for (int mi = 0; mi < 4; mi++) {
                    const int m0 = wmA * 64 + mi * 16;
                    tf32_split(Stg[(k0 + tg    ) * 264 + m0 + g    ], ah[mi][0], al[mi][0]);
                    tf32_split(Stg[(k0 + tg    ) * 264 + m0 + g + 8], ah[mi][1], al[mi][1]);
                    tf32_split(Stg[(k0 + tg + 4) * 264 + m0 + g    ], ah[mi][2], al[mi][2]);
                    tf32_split(Stg[(k0 + tg + 4) * 264 + m0 + g + 8], ah[mi][3], al[mi][3]);
                }
#pragma unroll
                for (int nj = 0; nj < 4; nj++) {
                    const int n0d = wnA * 32 + nj * 8;
                    tf32_split(Vs[(k0 + tg    ) * 72 + n0d + g], bhf[nj][0], blf[nj][0]);
                    tf32_split(Vs[(k0 + tg + 4) * 72 + n0d + g], bhf[nj][1], blf[nj][1]);
                }
#pragma unroll
                for (int mi = 0; mi < 4; mi++)
#pragma unroll
                    for (int nj = 0; nj < 4; nj++) mma_tf32(acc2[mi][nj], ah[mi], bhf[nj]);
#pragma unroll
                for (int mi = 0; mi < 4; mi++)
#pragma unroll
                    for (int nj = 0; nj < 4; nj++) mma_tf32(acc2[mi][nj], ah[mi], blf[nj]);
#pragma unroll
                for (int mi = 0; mi < 4; mi++)
#pragma unroll
                    for (int nj = 0; nj < 4; nj++) mma_tf32(acc2[mi][nj], al[mi], bhf[nj]);
            }
            __syncthreads();
        }
    }

    // ---- write partials
    const size_t pb = ((size_t)bh * CH_ + ch) * M_;
#pragma unroll
    for (int mi = 0; mi < 4; mi++) {
        const int feat = wmA * 64 + mi * 16 + g;
#pragma unroll
        for (int nj = 0; nj < 4; nj++) {
            const int dk = wnA * 32 + nj * 8 + tg * 2;
            *(float2*)(g_Spart + (pb + feat) * DK_ + dk) =
                make_float2(acc2[mi][nj][0], acc2[mi][nj][1]);
            *(float2*)(g_Spart + (pb + feat + 8) * DK_ + dk) =
                make_float2(acc2[mi][nj][2], acc2[mi][nj][3]);
        }
    }
    g_Kpart[pb + t] = ksacc;
}

// ============ kernel 3b: deterministic chunk reduction ===================
__global__ void k_sreduce() {
    const int tot = BH_ * M_ * (DK_ + 1);
    int idx = blockIdx.x * 256 + threadIdx.x;
    if (idx >= tot) return;
    int bh  = idx / (M_ * (DK_ + 1));
    int rem = idx % (M_ * (DK_ + 1));
    int m = rem / (DK_ + 1);
    int d = rem % (DK_ + 1);
    if (d < DK_) {
        float s = 0.0f;
#pragma unroll
        for (int c = 0; c < CH_; c++)
            s += g_Spart[(((size_t)bh * CH_ + c) * M_ + m) * DK_ + d];
        g_S[((size_t)bh * M_ + m) * DK_ + d] = s;
    } else {
        float s = 0.0f;
#pragma unroll
        for (int c = 0; c < CH_; c++)
            s += g_Kpart[((size_t)bh * CH_ + c) * M_ + m];
        g_Ksum[(size_t)bh * M_ + m] = s;
    }
}

// ====== kernel B: phi(Q) fused with ctx = (Qf S)/(Qf Ksum + eps) ========
// grid (BH, N/64). Per block: 64 rows; phi in regs, then 4 feature-slabs:
// stage Qf slab (exp), mma vs S slab, scalar denom vs Ksum slab.
__global__ __launch_bounds__(256) void k_phiq_ctx(const float* __restrict__ omega) {
    __shared__ __align__(16) float pool[11520];
    __shared__ float s_max[4][64];
    __shared__ float s_sq[64];
    __shared__ float s_den[64];
    __shared__ float Kss[64];
    float* Ts  = pool;            // [64][36]
    float* Om  = pool + 2304;     // [256][36]
    float* Stg = pool;            // [64][68] alias
    float* Ss  = pool + 4352;     // [64][72]

    const int t = threadIdx.x, lane = t & 31, wid = t >> 5;
    const int g = lane >> 2, tg = lane & 3;
    const int wm = wid >> 2, wn = wid & 3;       // shared grid 2m x 4n
    const int bh = blockIdx.x;
    const int n0 = blockIdx.y * 64;
    const int h = bh & (H_ - 1), bI = bh >> 4;
    const float invs = rsqrtf(256.0f + 1e-6f);

    float acc[2][8][4];
#pragma unroll
    for (int mi = 0; mi < 2; mi++)
#pragma unroll
        for (int nj = 0; nj < 8; nj++)
#pragma unroll
            for (int e = 0; e < 4; e++) acc[mi][nj][e] = 0.0f;
    float accC[2][2][4];
#pragma unroll
    for (int mi = 0; mi < 2; mi++)
#pragma unroll
        for (int nj = 0; nj < 2; nj++)
#pragma unroll
            for (int e = 0; e < 4; e++) accC[mi][nj][e] = 0.0f;
    float dpart = 0.0f;

    // ---- phi(Q)
    for (int kp = 0; kp < 2; kp++) {
        const int k0g = kp * 32;
        __syncthreads();
#pragma unroll
        for (int it = 0; it < 2; it++) {
            int f = it * 256 + t;
            int r = f >> 3, q = f & 7;
            float4 v = *(const float4*)(g_Q + ((size_t)bh * N_ + n0 + r) * DK_ + k0g + q * 4);
            *(float4*)(Ts + r * 36 + q * 4) = v;
        }
#pragma unroll
        for (int it = 0; it < 8; it++) {
            int f = it * 256 + t;
            int r = f >> 3, q = f & 7;
            float4 v = *(const float4*)(omega + ((size_t)h * M_ + r) * DK_ + k0g + q * 4);
            *(float4*)(Om + r * 36 + q * 4) = v;
        }
        __syncthreads();
        if (t < 64) {
            float ssum = 0.0f;
#pragma unroll
            for (int k = 0; k < 32; k++) { float q = Ts[t * 36 + k]; ssum += q * q; }
            if (kp == 0) s_sq[t] = ssum; else s_sq[t] += ssum;
        }
#pragma unroll
        for (int ks = 0; ks < 4; ks++) {
            const int k0 = ks * 8;
            uint32_t ah[2][4], al[2][4], obh[8][2], obl[8][2];
#pragma unroll
            for (int mi = 0; mi < 2; mi++) {
                const int m0 = wm * 32 + mi * 16;
                tf32_split(Ts[(m0 + g    ) * 36 + k0 + tg    ], ah[mi][0], al[mi][0]);
                tf32_split(Ts[(m0 + g + 8) * 36 + k0 + tg    ], ah[mi][1], al[mi][1]);
                tf32_split(Ts[(m0 + g    ) * 36 + k0 + tg + 4], ah[mi][2], al[mi][2]);
                tf32_split(Ts[(m0 + g + 8) * 36 + k0 + tg + 4], ah[mi][3], al[mi][3]);
            }
#pragma unroll
            for (int nj = 0; nj < 8; nj++) {
                const int nc = wn * 64 + nj * 8;
                tf32_split(Om[(nc + g) * 36 + k0 + tg    ], obh[nj][0], obl[nj][0]);
                tf32_split(Om[(nc + g) * 36 + k0 + tg + 4], obh[nj][1], obl[nj][1]);
            }
#pragma unroll
            for (int mi = 0; mi < 2; mi++)
#pragma unroll
                for (int nj = 0; nj < 8; nj++) mma_tf32(acc[mi][nj], ah[mi], obh[nj]);
#pragma unroll
            for (int mi = 0; mi < 2; mi++)
#pragma unroll
                for (int nj = 0; nj < 8; nj++) mma_tf32(acc[mi][nj], ah[mi], obl[nj]);
#pragma unroll
            for (int mi = 0; mi < 2; mi++)
#pragma unroll
                for (int nj = 0; nj < 8; nj++) mma_tf32(acc[mi][nj], al[mi], obh[nj]);
        }
    }
    // ---- row-max
#pragma unroll
    for (int mi = 0; mi < 2; mi++) {
#pragma unroll
        for (int half = 0; half < 2; half++) {
            float m = acc[mi][0][half * 2];
#pragma unroll
            for (int nj = 0; nj < 8; nj++) {
                m = fmaxf(m, acc[mi][nj][half * 2]);
                m = fmaxf(m, acc[mi][nj][half * 2 + 1]);
            }
            m = fmaxf(m, __shfl_xor_sync(0xffffffffu, m, 1));
            m = fmaxf(m, __shfl_xor_sync(0xffffffffu, m, 2));
            if (tg == 0) s_max[wn][wm * 32 + mi * 16 + half * 8 + g] = m;
        }
    }
    __syncthreads();

    // ---- feature slabs
    for (int s = 0; s < 4; s++) {
        if (s) __syncthreads();
        if (wn == s) {                 // this warp column owns feats [64s,64s+64)
#pragma unroll
            for (int mi = 0; mi < 2; mi++)
#pragma unroll
            for (int half = 0; half < 2; half++) {
                const int rg = wm * 32 + mi * 16 + half * 8 + g;
                float rm = fmaxf(fmaxf(s_max[0][rg], s_max[1][rg]),
                                 fmaxf(s_max[2][rg], s_max[3][rg]));
                float e = -rm - 0.5f * s_sq[rg];
#pragma unroll
                for (int nj = 0; nj < 8; nj++) {
                    const int col = nj * 8 + tg * 2;
                    *(float2*)(Stg + rg * 68 + col) = make_float2(
                        expf(acc[mi][nj][half * 2    ] + e) * invs,
                        expf(acc[mi][nj][half * 2 + 1] + e) * invs);
                }
            }
        }
#pragma unroll
        for (int it = 0; it < 4; it++) {   // S slab 64 feats x 64 dk
            int f = it * 256 + t;
            int r = f >> 4, dq = f & 15;
            float4 v = *(const float4*)(g_S + ((size_t)bh * M_ + s * 64 + r) * DK_ + dq * 4);
            *(float4*)(Ss + r * 72 + dq * 4) = v;
        }
        if (t < 64) Kss[t] = g_Ksum[(size_t)bh * M_ + s * 64 + t];
        __syncthreads();
        {   // denom partial: thread t -> row t>>2, feat group t&3
            const int r = t >> 2, fg = (t & 3) * 16;
#pragma unroll
            for (int i = 0; i < 16; i++)
                dpart = fmaf(Stg[r * 68 + fg + i], Kss[fg + i], dpart);
        }
#pragma unroll
        for (int ks = 0; ks < 8; ks++) {
            const int k0 = ks * 8;
            uint32_t ah[2][4], al[2][4], bhf[2][2], blf[2][2];
#pragma unroll
            for (int mi = 0; mi < 2; mi++) {
                const int m0 = wm * 32 + mi * 16;
                tf32_split(Stg[(m0 + g    ) * 68 + k0 + tg    ], ah[mi][0], al[mi][0]);
                tf32_split(Stg[(m0 + g + 8) * 68 + k0 + tg    ], ah[mi][1], al[mi][1]);
                tf32_split(Stg[(m0 + g    ) * 68 + k0 + tg + 4], ah[mi][2], al[mi][2]);
                tf32_split(Stg[(m0 + g + 8) * 68 + k0 + tg + 4], ah[mi][3], al[mi][3]);
            }
#pragma unroll
            for (int nj = 0; nj < 2; nj++) {
                const int n0d = wn * 16 + nj * 8;
                tf32_split(Ss[(k0 + tg    ) * 72 + n0d + g], bhf[nj][0], blf[nj][0]);
                tf32_split(Ss[(k0 + tg + 4) * 72 + n0d + g], bhf[nj][1], blf[nj][1]);
            }
#pragma unroll
            for (int mi = 0; mi < 2; mi++)
#pragma unroll
                for (int nj = 0; nj < 2; nj++) mma_tf32(accC[mi][nj], ah[mi], bhf[nj]);
#pragma unroll
            for (int mi = 0; mi < 2; mi++)
#pragma unroll
                for (int nj = 0; nj < 2; nj++) mma_tf32(accC[mi][nj], ah[mi], blf[nj]);
#pragma unroll
            for (int mi = 0; mi < 2; mi++)
#pragma unroll
                for (int nj = 0; nj < 2; nj++) mma_tf32(accC[mi][nj], al[mi], bhf[nj]);
        }
    }
    // denom reduce over the 4 feature groups (lanes l, l^1, l^2 share row)
    dpart += __shfl_xor_sync(0xffffffffu, dpart, 1);
    dpart += __shfl_xor_sync(0xffffffffu, dpart, 2);
    if ((t & 3) == 0) s_den[t >> 2] = dpart;
    __syncthreads();

    // ---- epilogue: divide, mask, write ctx
#pragma unroll
    for (int mi = 0; mi < 2; mi++) {
        const int r0 = wm * 32 + mi * 16 + g;
#pragma unroll
        for (int nj = 0; nj < 2; nj++) {
            const int dk = wn * 16 + nj * 8 + tg * 2;
#pragma unroll
            for (int half = 0; half < 2; half++) {
                const int r = r0 + half * 8;
                const float vv = g_valid[bI * N_ + n0 + r];
                const float dn = vv / (s_den[r] + 1e-6f);
                *(float2*)(g_ctx + ((size_t)bI * N_ + n0 + r) * D_ + h * DK_ + dk) =
                    make_float2(accC[mi][nj][half * 2] * dn,
                                accC[mi][nj][half * 2 + 1] * dn);
            }
        }
    }
}

// ========================= launch ========================================
extern "C" void kernel_launch(void* const* d_in, const int* in_sizes, int n_in,
                              void* d_out, int out_size) {
    (void)in_sizes; (void)n_in; (void)out_size;
    const float* x     = (const float*)d_in[0];
    const float* Wqkv  = (const float*)d_in[1];
    const float* bqkv  = (const float*)d_in[2];
    const float* Wout  = (const float*)d_in[3];
    const float* bout  = (const float*)d_in[4];
    const float* omega = (const float*)d_in[5];
    const void*  mask  = d_in[6];
    float* out = (float*)d_out;

    k_mask<<<1, 256>>>(mask);
    k_gemm_mma<<<dim3(24, 128), 256>>>(x, Wqkv, bqkv, nullptr, 0);
    k_phik_spart<<<dim3(BH_, CH_), 256>>>(omega);
    {
        const int tot = BH_ * M_ * (DK_ + 1);
        k_sreduce<<<(tot + 255) / 256, 256>>>();
    }
    k_phiq_ctx<<<dim3(BH_, N_ / 64), 256>>>(omega);
    k_gemm_mma<<<dim3(8, 128), 256>>>(x, Wout, bout, out, 1);
}

// round 10
// speedup vs baseline: 1.4096x; 1.0049x over previous
#include <cuda_runtime.h>
#include <cstdint>
#include <math.h>

// FAVOR+ attention  B=4,N=4096,D=1024,H=16,dk=64,M=256
// R10 = R9 + (1) ex2.approx fast exp, (2) omega pre-split to global
// fragment-layout hi/lo (kills all omega smem staging + splits in the
// fused kernels). Structure otherwise identical to passing R9.

namespace {
constexpr int B_  = 4;
constexpr int N_  = 4096;
constexpr int D_  = 1024;
constexpr int H_  = 16;
constexpr int DK_ = 64;
constexpr int M_  = 256;
constexpr int BH_ = B_ * H_;
constexpr int CH_ = 16;
}

// -------- device scratch --------
__device__ float g_valid[B_ * N_];
__device__ float g_Q[BH_ * N_ * DK_];
__device__ float g_K[BH_ * N_ * DK_];
__device__ float g_V[BH_ * N_ * DK_];
__device__ float g_Spart[(size_t)BH_ * CH_ * M_ * DK_];
__device__ float g_Kpart[BH_ * CH_ * M_];
__device__ float g_S[BH_ * M_ * DK_];
__device__ float g_Ksum[BH_ * M_];
__device__ float g_ctx[(size_t)B_ * N_ * D_];
// omega pre-split, fragment layout: [h][ks(8)][m(256)][tg(4)] uint4 =
// {hi(k0+tg), hi(k0+tg+4), lo(k0+tg), lo(k0+tg+4)}, k0 = ks*8. 2MB.
__device__ uint4 g_omf[H_ * 8 * M_ * 4];

// ---- helpers ----
__device__ __forceinline__ uint32_t smem_u32(const void* p) {
    uint32_t a;
    asm("{ .reg .u64 t; cvta.to.shared.u64 t, %1; cvt.u32.u64 %0, t; }"
        : "=r"(a) : "l"(p));
    return a;
}
__device__ __forceinline__ void cp_async16(void* sdst, const void* gsrc) {
    asm volatile("cp.async.cg.shared.global [%0], [%1], 16;"
                 :: "r"(smem_u32(sdst)), "l"(gsrc) : "memory");
}
__device__ __forceinline__ void tf32_split(float f, uint32_t& h, uint32_t& l) {
    uint32_t hb;
    asm("cvt.rna.tf32.f32 %0, %1;" : "=r"(hb) : "f"(f));
    float lf = f - __uint_as_float(hb);
    uint32_t lb;
    asm("cvt.rna.tf32.f32 %0, %1;" : "=r"(lb) : "f"(lf));
    h = hb; l = lb;
}
__device__ __forceinline__ float fexp(float x) {
    float y;
    asm("ex2.approx.f32 %0, %1;" : "=f"(y) : "f"(x * 1.4426950408889634f));
    return y;
}
__device__ __forceinline__ void mma_tf32(float* c, const uint32_t* a, const uint32_t* b) {
    asm volatile(
        "mma.sync.aligned.m16n8k8.row.col.f32.tf32.tf32.f32 "
        "{%0,%1,%2,%3}, {%4,%5,%6,%7}, {%8,%9}, {%0,%1,%2,%3};"
        : "+f"(c[0]), "+f"(c[1]), "+f"(c[2]), "+f"(c[3])
        : "r"(a[0]), "r"(a[1]), "r"(a[2]), "r"(a[3]), "r"(b[0]), "r"(b[1]));
}

// ============ omega pre-split (once per launch, ~3us) ====================
__global__ void k_omsplit(const float* __restrict__ omega) {
    int idx = blockIdx.x * 256 + threadIdx.x;    // = h*8192 + ks*1024 + m*4 + tg
    if (idx >= H_ * 8 * M_ * 4) return;
    int tg = idx & 3;
    int m  = (idx >> 2) & 255;
    int ks = (idx >> 10) & 7;
    int h  = idx >> 13;
    const float* row = omega + ((size_t)h * M_ + m) * DK_ + ks * 8;
    uint32_t h0, l0, h1, l1;
    tf32_split(row[tg], h0, l0);
    tf32_split(row[tg + 4], h1, l1);
    g_omf[idx] = make_uint4(h0, h1, l0, l1);
}

// ============ mma.sync TF32 3x GEMM: C(128x128 tile) = A @ Bw^T ==========
__global__ __launch_bounds__(256) void k_gemm_mma(const float* __restrict__ A,
                                                  const float* __restrict__ Bw,
                                                  const float* __restrict__ bias,
                                                  float* __restrict__ Cp,
                                                  int mode) {
    __shared__ __align__(16) float As[2][128][20];
    __shared__ __align__(16) float Bs[2][128][20];
    const int t = threadIdx.x;
    const int lane = t & 31, wid = t >> 5;
    const int g = lane >> 2, tg = lane & 3;
    const int wm = wid >> 2, wn = wid & 3;
    const int rb = blockIdx.y * 128, cb = blockIdx.x * 128;
    constexpr int K = 1024;
    constexpr int NSLAB = K / 16;
    const float* Ap = (mode == 1) ? (const float*)g_ctx : A;

    float acc[4][4][4];
#pragma unroll
    for (int i = 0; i < 4; i++)
#pragma unroll
        for (int j = 0; j < 4; j++)
#pragma unroll
            for (int e = 0; e < 4; e++) acc[i][j][e] = 0.0f;

    {
#pragma unroll
        for (int it = 0; it < 2; it++) {
            int f = it * 256 + t;
            int r = f >> 2, q = f & 3;
            cp_async16(&As[0][r][q * 4], Ap + (size_t)(rb + r) * K + q * 4);
            cp_async16(&Bs[0][r][q * 4], Bw + (size_t)(cb + r) * K + q * 4);
        }
        asm volatile("cp.async.commit_group;" ::: "memory");
    }

    for (int sl = 0; sl < NSLAB; sl++) {
        const int st = sl & 1;
        if (sl + 1 < NSLAB) {
            const int kt = (sl + 1) * 16;
            const int ns = st ^ 1;
#pragma unroll
            for (int it = 0; it < 2; it++) {
                int f = it * 256 + t;
                int r = f >> 2, q = f & 3;
                cp_async16(&As[ns][r][q * 4], Ap + (size_t)(rb + r) * K + kt + q * 4);
                cp_async16(&Bs[ns][r][q * 4], Bw + (size_t)(cb + r) * K + kt + q * 4);
            }
            asm volatile("cp.async.commit_group;" ::: "memory");
            asm volatile("cp.async.wait_group 1;" ::: "memory");
        } else {
            asm volatile("cp.async.wait_group 0;" ::: "memory");
        }
        __syncthreads();

#pragma unroll
        for (int ks = 0; ks < 2; ks++) {
            const int k0 = ks * 8;
            uint32_t ah[4][4], al[4][4], bh[4][2], bl[4][2];
#pragma unroll
            for (int i = 0; i < 4; i++) {
                const int m0 = wm * 64 + i * 16;
                tf32_split(As[st][m0 + g    ][k0 + tg    ], ah[i][0], al[i][0]);
                tf32_split(As[st][m0 + g + 8][k0 + tg    ], ah[i][1], al[i][1]);
                tf32_split(As[st][m0 + g    ][k0 + tg + 4], ah[i][2], al[i][2]);
                tf32_split(As[st][m0 + g + 8][k0 + tg + 4], ah[i][3], al[i][3]);
            }
#pragma unroll
            for (int j = 0; j < 4; j++) {
                const int n0 = wn * 32 + j * 8;
                tf32_split(Bs[st][n0 + g][k0 + tg    ], bh[j][0], bl[j][0]);
                tf32_split(Bs[st][n0 + g][k0 + tg + 4], bh[j][1], bl[j][1]);
            }
#pragma unroll
            for (int i = 0; i < 4; i++)
#pragma unroll
                for (int j = 0; j < 4; j++) mma_tf32(acc[i][j], ah[i], bh[j]);
#pragma unroll
            for (int i = 0; i < 4; i++)
#pragma unroll
                for (int j = 0; j < 4; j++) mma_tf32(acc[i][j], ah[i], bl[j]);
#pragma unroll
            for (int i = 0; i < 4; i++)
#pragma unroll
                for (int j = 0; j < 4; j++) mma_tf32(acc[i][j], al[i], bh[j]);
        }
        __syncthreads();
    }

#pragma unroll
    for (int i = 0; i < 4; i++) {
        const int r0 = rb + wm * 64 + i * 16 + g;
#pragma unroll
        for (int j = 0; j < 4; j++) {
            const int c = cb + wn * 32 + j * 8 + tg * 2;
            const float b0 = bias[c], b1 = bias[c + 1];
            if (mode == 1) {
                *(float2*)(Cp + (size_t)r0 * 1024 + c) =
                    make_float2(acc[i][j][0] + b0, acc[i][j][1] + b1);
                *(float2*)(Cp + (size_t)(r0 + 8) * 1024 + c) =
                    make_float2(acc[i][j][2] + b0, acc[i][j][3] + b1);
            } else {
                const int which = c >> 10;
                const int hh = (c & 1023) >> 6;
                const int dk = c & 63;
#pragma unroll
                for (int half = 0; half < 2; half++) {
                    const int r = r0 + half * 8;
                    const float vv = g_valid[r];
                    const float v0 = acc[i][j][half * 2 + 0] + b0;
                    const float v1 = acc[i][j][half * 2 + 1] + b1;
                    size_t off = ((((size_t)(r >> 12)) * H_ + hh) * N_ + (r & 4095)) * DK_ + dk;
                    if (which == 0)
                        *(float2*)(g_Q + off) = make_float2(v0 * vv, v1 * vv);
                    else if (which == 1)
                        *(float2*)(g_K + off) = make_float2(v0, v1);
                    else
                        *(float2*)(g_V + off) = make_float2(v0 * vv, v1 * vv);
                }
            }
        }
    }
}

// ===================== kernel 0: mask -> valid ==========================
__global__ void k_mask(const void* __restrict__ mask) {
    __shared__ int sF, sOdd;
    const int t = threadIdx.x;
    if (t == 0) { sF = 0; sOdd = 0; }
    __syncthreads();
    const unsigned* w = (const unsigned*)mask;
    for (int i = t; i < 4096; i += 256) {
        unsigned v = w[i];
        if (v == 0x3F800000u) sF = 1;
        else if (v != 0u && v != 1u) sOdd = 1;
    }
    __syncthreads();
    if (sF) {
        const float* m = (const float*)mask;
        for (int i = t; i < B_ * N_; i += 256)
            g_valid[i] = (m[i] != 0.0f) ? 0.0f : 1.0f;
    } else if (sOdd) {
        const unsigned char* m = (const unsigned char*)mask;
        for (int i = t; i < B_ * N_; i += 256)
            g_valid[i] = m[i] ? 0.0f : 1.0f;
    } else {
        const int* m = (const int*)mask;
        for (int i = t; i < B_ * N_; i += 256)
            g_valid[i] = m[i] ? 0.0f : 1.0f;
    }
}

// ====== kernel A: phi(K) fused with S/Ksum partial accumulation =========
// grid (BH, CH). Omega fragments sourced from g_omf (no smem staging).
__global__ __launch_bounds__(256) void k_phik_spart() {
    __shared__ __align__(16) float pool[10752];   // 43 KB
    __shared__ float s_max[4][64];
    __shared__ float s_sq[64];
    float* Ts  = pool;            // [64][36] (phi phase)
    float* Stg = pool;            // [32][264] alias
    float* Vs  = pool + 8448;     // [32][72]

    const int t = threadIdx.x, lane = t & 31, wid = t >> 5;
    const int g = lane >> 2, tg = lane & 3;
    const int wm = wid >> 2, wn = wid & 3;       // phi warp grid 2m x 4n
    const int wmA = wid >> 1, wnA = wid & 1;     // spart warp grid 4m x 2n
    const int bh = blockIdx.x, ch = blockIdx.y;
    const int h = bh & (H_ - 1), bI = bh >> 4;
    const float invs = rsqrtf(256.0f + 1e-6f);

    float acc2[4][4][4];
#pragma unroll
    for (int i = 0; i < 4; i++)
#pragma unroll
        for (int j = 0; j < 4; j++)
#pragma unroll
            for (int e = 0; e < 4; e++) acc2[i][j][e] = 0.0f;
    float ksacc = 0.0f;

    for (int tile = 0; tile < 4; tile++) {
        const int n0 = ch * 256 + tile * 64;
        float acc[2][8][4];
#pragma unroll
        for (int mi = 0; mi < 2; mi++)
#pragma unroll
            for (int nj = 0; nj < 8; nj++)
#pragma unroll
                for (int e = 0; e < 4; e++) acc[mi][nj][e] = 0.0f;

        for (int kp = 0; kp < 2; kp++) {
            const int k0g = kp * 32;
            __syncthreads();                      // pool reuse guard
#pragma unroll
            for (int it = 0; it < 2; it++) {
                int f = it * 256 + t;
                int r = f >> 3, q = f & 7;
                float4 v = *(const float4*)(g_K + ((size_t)bh * N_ + n0 + r) * DK_ + k0g + q * 4);
                *(float4*)(Ts + r * 36 + q * 4) = v;
            }
            __syncthreads();
            if (t < 64) {
                float ssum = 0.0f;
#pragma unroll
                for (int k = 0; k < 32; k++) { float q = Ts[t * 36 + k]; ssum += q * q; }
                if (kp == 0) s_sq[t] = ssum; else s_sq[t] += ssum;
            }
#pragma unroll
            for (int ks = 0; ks < 4; ks++) {
                const int k0 = ks * 8;
                const uint4* pb = g_omf + ((size_t)(h * 8 + kp * 4 + ks) << 10);
                uint32_t ah[2][4], al[2][4], obh[8][2], obl[8][2];
#pragma unroll
                for (int mi = 0; mi < 2; mi++) {
                    const int m0 = wm * 32 + mi * 16;
                    tf32_split(Ts[(m0 + g    ) * 36 + k0 + tg    ], ah[mi][0], al[mi][0]);
                    tf32_split(Ts[(m0 + g + 8) * 36 + k0 + tg    ], ah[mi][1], al[mi][1]);
                    tf32_split(Ts[(m0 + g    ) * 36 + k0 + tg + 4], ah[mi][2], al[mi][2]);
                    tf32_split(Ts[(m0 + g + 8) * 36 + k0 + tg + 4], ah[mi][3], al[mi][3]);
                }
#pragma unroll
                for (int nj = 0; nj < 8; nj++) {
                    uint4 v = pb[(wn * 64 + nj * 8 + g) * 4 + tg];
                    obh[nj][0] = v.x; obh[nj][1] = v.y;
                    obl[nj][0] = v.z; obl[nj][1] = v.w;
                }
#pragma unroll
                for (int mi = 0; mi < 2; mi++)
#pragma unroll
                    for (int nj = 0; nj < 8; nj++) mma_tf32(acc[mi][nj], ah[mi], obh[nj]);
#pragma unroll
                for (int mi = 0; mi < 2; mi++)
#pragma unroll
                    for (int nj = 0; nj < 8; nj++) mma_tf32(acc[mi][nj], ah[mi], obl[nj]);
#pragma unroll
                for (int mi = 0; mi < 2; mi++)
#pragma unroll
                    for (int nj = 0; nj < 8; nj++) mma_tf32(acc[mi][nj], al[mi], obh[nj]);
            }
        }
#pragma unroll
        for (int mi = 0; mi < 2; mi++) {
#pragma unroll
            for (int half = 0; half < 2; half++) {
                float m = acc[mi][0][half * 2];
#pragma unroll
                for (int nj = 0; nj < 8; nj++) {
                    m = fmaxf(m, acc[mi][nj][half * 2]);
                    m = fmaxf(m, acc[mi][nj][half * 2 + 1]);
                }
                m = fmaxf(m, __shfl_xor_sync(0xffffffffu, m, 1));
                m = fmaxf(m, __shfl_xor_sync(0xffffffffu, m, 2));
                if (tg == 0) s_max[wn][wm * 32 + mi * 16 + half * 8 + g] = m;
            }
        }
        __syncthreads();

        for (int hr = 0; hr < 2; hr++) {
            if (wm == hr) {
#pragma unroll
                for (int mi = 0; mi < 2; mi++)
#pragma unroll
                for (int half = 0; half < 2; half++) {
                    const int rloc = mi * 16 + half * 8 + g;
                    const int rg = hr * 32 + rloc;
                    float rm = fmaxf(fmaxf(s_max[0][rg], s_max[1][rg]),
                                     fmaxf(s_max[2][rg], s_max[3][rg]));
                    float e = -rm - 0.5f * s_sq[rg];
                    float sc = invs * g_valid[bI * N_ + n0 + rg];
#pragma unroll
                    for (int nj = 0; nj < 8; nj++) {
                        const int col = wn * 64 + nj * 8 + tg * 2;
                        *(float2*)(Stg + rloc * 264 + col) = make_float2(
                            fexp(acc[mi][nj][half * 2    ] + e) * sc,
                            fexp(acc[mi][nj][half * 2 + 1] + e) * sc);
                    }
                }
            }
#pragma unroll
            for (int it = 0; it < 2; it++) {
                int f = it * 256 + t;
                int r = f >> 4, dq = f & 15;
                float4 v = *(const float4*)(g_V + ((size_t)bh * N_ + n0 + hr * 32 + r) * DK_ + dq * 4);
                *(float4*)(Vs + r * 72 + dq * 4) = v;
            }
            __syncthreads();
#pragma unroll 8
            for (int r = 0; r < 32; r++) ksacc += Stg[r * 264 + t];
#pragma unroll
            for (int ks = 0; ks < 4; ks++) {
                const int k0 = ks * 8;
                uint32_t ah[4][4], al[4][4], bhf[4][2], blf[4][2];
#pragma unroll
                for (int mi = 0; mi < 4; mi++) {
                    const int m0 = wmA * 64 + mi * 16;
                    tf32_split(Stg[(k0 + tg    ) * 264 + m0 + g    ], ah[mi][0], al[mi][0]);
                    tf32_split(Stg[(k0 + tg    ) * 264 + m0 + g + 8], ah[mi][1], al[mi][1]);
                    tf32_split(Stg[(k0 + tg + 4) * 264 + m0 + g    ], ah[mi][2], al[mi][2]);
                    tf32_split(Stg[(k0 + tg + 4) * 264 + m0 + g + 8], ah[mi][3], al[mi][3]);
                }
#pragma unroll
                for (int nj = 0; nj < 4; nj++) {
                    const int n0d = wnA * 32 + nj * 8;
                    tf32_split(Vs[(k0 + tg    ) * 72 + n0d + g], bhf[nj][0], blf[nj][0]);
                    tf32_split(Vs[(k0 + tg + 4) * 72 + n0d + g], bhf[nj][1], blf[nj][1]);
                }
#pragma unroll
                for (int mi = 0; mi < 4; mi++)
#pragma unroll
                    for (int nj = 0; nj < 4; nj++) mma_tf32(acc2[mi][nj], ah[mi], bhf[nj]);
#pragma unroll
                for (int mi = 0; mi < 4; mi++)
#pragma unroll
                    for (int nj = 0; nj < 4; nj++) mma_tf32(acc2[mi][nj], ah[mi], blf[nj]);
#pragma unroll
                for (int mi = 0; mi < 4; mi++)
#pragma unroll
                    for (int nj = 0; nj < 4; nj++) mma_tf32(acc2[mi][nj], al[mi], bhf[nj]);
            }
            __syncthreads();
        }
    }

    const size_t pb = ((size_t)bh * CH_ + ch) * M_;
#pragma unroll
    for (int mi = 0; mi < 4; mi++) {
        const int feat = wmA * 64 + mi * 16 + g;
#pragma unroll
        for (int nj = 0; nj < 4; nj++) {
            const int dk = wnA * 32 + nj * 8 + tg * 2;
            *(float2*)(g_Spart + (pb + feat) * DK_ + dk) =
                make_float2(acc2[mi][nj][0], acc2[mi][nj][1]);
            *(float2*)(g_Spart + (pb + feat + 8) * DK_ + dk) =
                make_float2(acc2[mi][nj][2], acc2[mi][nj][3]);
        }
    }
    g_Kpart[pb + t] = ksacc;
}

// ============ kernel 3b: deterministic chunk reduction ===================
__global__ void k_sreduce() {
    const int tot = BH_ * M_ * (DK_ + 1);
    int idx = blockIdx.x * 256 + threadIdx.x;
    if (idx >= tot) return;
    int bh  = idx / (M_ * (DK_ + 1));
    int rem = idx % (M_ * (DK_ + 1));
    int m = rem / (DK_ + 1);
    int d = rem % (DK_ + 1);
    if (d < DK_) {
        float s = 0.0f;
#pragma unroll
        for (int c = 0; c < CH_; c++)
            s += g_Spart[(((size_t)bh * CH_ + c) * M_ + m) * DK_ + d];
        g_S[((size_t)bh * M_ + m) * DK_ + d] = s;
    } else {
        float s = 0.0f;
#pragma unroll
        for (int c = 0; c < CH_; c++)
            s += g_Kpart[((size_t)bh * CH_ + c) * M_ + m];
        g_Ksum[(size_t)bh * M_ + m] = s;
    }
}

// ====== kernel B: phi(Q) fused with ctx = (Qf S)/(Qf Ksum + eps) ========
__global__ __launch_bounds__(256) void k_phiq_ctx() {
    __shared__ __align__(16) float pool[8960];    // 35.8 KB
    __shared__ float s_max[4][64];
    __shared__ float s_sq[64];
    __shared__ float s_den[64];
    __shared__ float Kss[64];
    float* Ts  = pool;            // [64][36]
    float* Stg = pool;            // [64][68] alias
    float* Ss  = pool + 4352;     // [64][72]

    const int t = threadIdx.x, lane = t & 31, wid = t >> 5;
    const int g = lane >> 2, tg = lane & 3;
    const int wm = wid >> 2, wn = wid & 3;
    const int bh = blockIdx.x;
    const int n0 = blockIdx.y * 64;
    const int h = bh & (H_ - 1), bI = bh >> 4;
    const float invs = rsqrtf(256.0f + 1e-6f);

    float acc[2][8][4];
#pragma unroll
    for (int mi = 0; mi < 2; mi++)
#pragma unroll
        for (int nj = 0; nj < 8; nj++)
#pragma unroll
            for (int e = 0; e < 4; e++) acc[mi][nj][e] = 0.0f;
    float accC[2][2][4];
#pragma unroll
    for (int mi = 0; mi < 2; mi++)
#pragma unroll
        for (int nj = 0; nj < 2; nj++)
#pragma unroll
            for (int e = 0; e < 4; e++) accC[mi][nj][e] = 0.0f;
    float dpart = 0.0f;

    for (int kp = 0; kp < 2; kp++) {
        const int k0g = kp * 32;
        __syncthreads();
#pragma unroll
        for (int it = 0; it < 2; it++) {
            int f = it * 256 + t;
            int r = f >> 3, q = f & 7;
            float4 v = *(const float4*)(g_Q + ((size_t)bh * N_ + n0 + r) * DK_ + k0g + q * 4);
            *(float4*)(Ts + r * 36 + q * 4) = v;
        }
        __syncthreads();
        if (t < 64) {
            float ssum = 0.0f;
#pragma unroll
            for (int k = 0; k < 32; k++) { float q = Ts[t * 36 + k]; ssum += q * q; }
            if (kp == 0) s_sq[t] = ssum; else s_sq[t] += ssum;
        }
#pragma unroll
        for (int ks = 0; ks < 4; ks++) {
            const int k0 = ks * 8;
            const uint4* pb = g_omf + ((size_t)(h * 8 + kp * 4 + ks) << 10);
            uint32_t ah[2][4], al[2][4], obh[8][2], obl[8][2];
#pragma unroll
            for (int mi = 0; mi < 2; mi++) {
                const int m0 = wm * 32 + mi * 16;
                tf32_split(Ts[(m0 + g    ) * 36 + k0 + tg    ], ah[mi][0], al[mi][0]);
                tf32_split(Ts[(m0 + g + 8) * 36 + k0 + tg    ], ah[mi][1], al[mi][1]);
                tf32_split(Ts[(m0 + g    ) * 36 + k0 + tg + 4], ah[mi][2], al[mi][2]);
                tf32_split(Ts[(m0 + g + 8) * 36 + k0 + tg + 4], ah[mi][3], al[mi][3]);
            }
#pragma unroll
            for (int nj = 0; nj < 8; nj++) {
                uint4 v = pb[(wn * 64 + nj * 8 + g) * 4 + tg];
                obh[nj][0] = v.x; obh[nj][1] = v.y;
                obl[nj][0] = v.z; obl[nj][1] = v.w;
            }
#pragma unroll
            for (int mi = 0; mi < 2; mi++)
#pragma unroll
                for (int nj = 0; nj < 8; nj++) mma_tf32(acc[mi][nj], ah[mi], obh[nj]);
#pragma unroll
            for (int mi = 0; mi < 2; mi++)
#pragma unroll
                for (int nj = 0; nj < 8; nj++) mma_tf32(acc[mi][nj], ah[mi], obl[nj]);
#pragma unroll
            for (int mi = 0; mi < 2; mi++)
#pragma unroll
                for (int nj = 0; nj < 8; nj++) mma_tf32(acc[mi][nj], al[mi], obh[nj]);
        }
    }
#pragma unroll
    for (int mi = 0; mi < 2; mi++) {
#pragma unroll
        for (int half = 0; half < 2; half++) {
            float m = acc[mi][0][half * 2];
#pragma unroll
            for (int nj = 0; nj < 8; nj++) {
                m = fmaxf(m, acc[mi][nj][half * 2]);
                m = fmaxf(m, acc[mi][nj][half * 2 + 1]);
            }
            m = fmaxf(m, __shfl_xor_sync(0xffffffffu, m, 1));
            m = fmaxf(m, __shfl_xor_sync(0xffffffffu, m, 2));
            if (tg == 0) s_max[wn][wm * 32 + mi * 16 + half * 8 + g] = m;
        }
    }
    __syncthreads();

    for (int s = 0; s < 4; s++) {
        if (s) __syncthreads();
        if (wn == s) {
#pragma unroll
            for (int mi = 0; mi < 2; mi++)
#pragma unroll
            for (int half = 0; half < 2; half++) {
                const int rg = wm * 32 + mi * 16 + half * 8 + g;
                float rm = fmaxf(fmaxf(s_max[0][rg], s_max[1][rg]),
                                 fmaxf(s_max[2][rg], s_max[3][rg]));
                float e = -rm - 0.5f * s_sq[rg];
#pragma unroll
                for (int nj = 0; nj < 8; nj++) {
                    const int col = nj * 8 + tg * 2;
                    *(float2*)(Stg + rg * 68 + col) = make_float2(
                        fexp(acc[mi][nj][half * 2    ] + e) * invs,
                        fexp(acc[mi][nj][half * 2 + 1] + e) * invs);
                }
            }
        }
#pragma unroll
        for (int it = 0; it < 4; it++) {
            int f = it * 256 + t;
            int r = f >> 4, dq = f & 15;
            float4 v = *(const float4*)(g_S + ((size_t)bh * M_ + s * 64 + r) * DK_ + dq * 4);
            *(float4*)(Ss + r * 72 + dq * 4) = v;
        }
        if (t < 64) Kss[t] = g_Ksum[(size_t)bh * M_ + s * 64 + t];
        __syncthreads();
        {
            const int r = t >> 2, fg = (t & 3) * 16;
#pragma unroll
            for (int i = 0; i < 16; i++)
                dpart = fmaf(Stg[r * 68 + fg + i], Kss[fg + i], dpart);
        }
#pragma unroll
        for (int ks = 0; ks < 8; ks++) {
            const int k0 = ks * 8;
            uint32_t ah[2][4], al[2][4], bhf[2][2], blf[2][2];
#pragma unroll
            for (int mi = 0; mi < 2; mi++) {
                const int m0 = wm * 32 + mi * 16;
                tf32_split(Stg[(m0 + g    ) * 68 + k0 + tg    ], ah[mi][0], al[mi][0]);
                tf32_split(Stg[(m0 + g + 8) * 68 + k0 + tg    ], ah[mi][1], al[mi][1]);
                tf32_split(Stg[(m0 + g    ) * 68 + k0 + tg + 4], ah[mi][2], al[mi][2]);
                tf32_split(Stg[(m0 + g + 8) * 68 + k0 + tg + 4], ah[mi][3], al[mi][3]);
            }
#pragma unroll
            for (int nj = 0; nj < 2; nj++) {
                const int n0d = wn * 16 + nj * 8;
                tf32_split(Ss[(k0 + tg    ) * 72 + n0d + g], bhf[nj][0], blf[nj][0]);
                tf32_split(Ss[(k0 + tg + 4) * 72 + n0d + g], bhf[nj][1], blf[nj][1]);
            }
#pragma unroll
            for (int mi = 0; mi < 2; mi++)
#pragma unroll
                for (int nj = 0; nj < 2; nj++) mma_tf32(accC[mi][nj], ah[mi], bhf[nj]);
#pragma unroll
            for (int mi = 0; mi < 2; mi++)
#pragma unroll
                for (int nj = 0; nj < 2; nj++) mma_tf32(accC[mi][nj], ah[mi], blf[nj]);
#pragma unroll
            for (int mi = 0; mi < 2; mi++)
#pragma unroll
                for (int nj = 0; nj < 2; nj++) mma_tf32(accC[mi][nj], al[mi], bhf[nj]);
        }
    }
    dpart += __shfl_xor_sync(0xffffffffu, dpart, 1);
    dpart += __shfl_xor_sync(0xffffffffu, dpart, 2);
    if ((t & 3) == 0) s_den[t >> 2] = dpart;
    __syncthreads();

#pragma unroll
    for (int mi = 0; mi < 2; mi++) {
        const int r0 = wm * 32 + mi * 16 + g;
#pragma unroll
        for (int nj = 0; nj < 2; nj++) {
            const int dk = wn * 16 + nj * 8 + tg * 2;
#pragma unroll
            for (int half = 0; half < 2; half++) {
                const int r = r0 + half * 8;
                const float vv = g_valid[bI * N_ + n0 + r];
                const float dn = vv / (s_den[r] + 1e-6f);
                *(float2*)(g_ctx + ((size_t)bI * N_ + n0 + r) * D_ + h * DK_ + dk) =
                    make_float2(accC[mi][nj][half * 2] * dn,
                                accC[mi][nj][half * 2 + 1] * dn);
            }
        }
    }
}

// ========================= launch ========================================
extern "C" void kernel_launch(void* const* d_in, const int* in_sizes, int n_in,
                              void* d_out, int out_size) {
    (void)in_sizes; (void)n_in; (void)out_size;
    const float* x     = (const float*)d_in[0];
    const float* Wqkv  = (const float*)d_in[1];
    const float* bqkv  = (const float*)d_in[2];
    const float* Wout  = (const float*)d_in[3];
    const float* bout  = (const float*)d_in[4];
    const float* omega = (const float*)d_in[5];
    const void*  mask  = d_in[6];
    float* out = (float*)d_out;

    k_mask<<<1, 256>>>(mask);
    k_omsplit<<<512, 256>>>(omega);
    k_gemm_mma<<<dim3(24, 128), 256>>>(x, Wqkv, bqkv, nullptr, 0);
    k_phik_spart<<<dim3(BH_, CH_), 256>>>();
    {
        const int tot = BH_ * M_ * (DK_ + 1);
        k_sreduce<<<(tot + 255) / 256, 256>>>();
    }
    k_phiq_ctx<<<dim3(BH_, N_ / 64), 256>>>();
    k_gemm_mma<<<dim3(8, 128), 256>>>(x, Wout, bout, out, 1);
}

// round 12
// speedup vs baseline: 1.4752x; 1.0465x over previous
#include <cuda_runtime.h>
#include <cstdint>
#include <math.h>

// FAVOR+ attention  B=4,N=4096,D=1024,H=16,dk=64,M=256
// R12 = R11 resubmission (R11 never ran: brokered-container infra flake,
// same as R0/R2/R4/R8; both prior unchanged resubmits R5/R9 ran clean).
// R11 change: post-exp linear algebra (spart / ctx mma) demoted from
// tf32-3x to tf32-1x with operands pre-rounded to tf32 at smem-store time
// (fragment loads become raw LDS). phi projections + weight GEMMs stay 3x.

namespace {
constexpr int B_  = 4;
constexpr int N_  = 4096;
constexpr int D_  = 1024;
constexpr int H_  = 16;
constexpr int DK_ = 64;
constexpr int M_  = 256;
constexpr int BH_ = B_ * H_;
constexpr int CH_ = 16;
}

// -------- device scratch --------
__device__ float g_valid[B_ * N_];
__device__ float g_Q[BH_ * N_ * DK_];
__device__ float g_K[BH_ * N_ * DK_];
__device__ float g_V[BH_ * N_ * DK_];
__device__ float g_Spart[(size_t)BH_ * CH_ * M_ * DK_];
__device__ float g_Kpart[BH_ * CH_ * M_];
__device__ float g_S[BH_ * M_ * DK_];
__device__ float g_Ksum[BH_ * M_];
__device__ float g_ctx[(size_t)B_ * N_ * D_];
// omega pre-split, fragment layout: [h][ks(8)][m(256)][tg(4)] uint4
__device__ uint4 g_omf[H_ * 8 * M_ * 4];

// ---- helpers ----
__device__ __forceinline__ uint32_t smem_u32(const void* p) {
    uint32_t a;
    asm("{ .reg .u64 t; cvta.to.shared.u64 t, %1; cvt.u32.u64 %0, t; }"
        : "=r"(a) : "l"(p));
    return a;
}
__device__ __forceinline__ void cp_async16(void* sdst, const void* gsrc) {
    asm volatile("cp.async.cg.shared.global [%0], [%1], 16;"
                 :: "r"(smem_u32(sdst)), "l"(gsrc) : "memory");
}
__device__ __forceinline__ void tf32_split(float f, uint32_t& h, uint32_t& l) {
    uint32_t hb;
    asm("cvt.rna.tf32.f32 %0, %1;" : "=r"(hb) : "f"(f));
    float lf = f - __uint_as_float(hb);
    uint32_t lb;
    asm("cvt.rna.tf32.f32 %0, %1;" : "=r"(lb) : "f"(lf));
    h = hb; l = lb;
}
__device__ __forceinline__ float tf32r(float f) {   // round-to-tf32, keep fp32
    uint32_t hb;
    asm("cvt.rna.tf32.f32 %0, %1;" : "=r"(hb) : "f"(f));
    return __uint_as_float(hb);
}
__device__ __forceinline__ float fexp(float x) {
    float y;
    asm("ex2.approx.f32 %0, %1;" : "=f"(y) : "f"(x * 1.4426950408889634f));
    return y;
}
__device__ __forceinline__ void mma_tf32(float* c, const uint32_t* a, const uint32_t* b) {
    asm volatile(
        "mma.sync.aligned.m16n8k8.row.col.f32.tf32.tf32.f32 "
        "{%0,%1,%2,%3}, {%4,%5,%6,%7}, {%8,%9}, {%0,%1,%2,%3};"
        : "+f"(c[0]), "+f"(c[1]), "+f"(c[2]), "+f"(c[3])
        : "r"(a[0]), "r"(a[1]), "r"(a[2]), "r"(a[3]), "r"(b[0]), "r"(b[1]));
}

// ============ omega pre-split (once per launch) ==========================
__global__ void k_omsplit(const float* __restrict__ omega) {
    int idx = blockIdx.x * 256 + threadIdx.x;
    if (idx >= H_ * 8 * M_ * 4) return;
    int tg = idx & 3;
    int m  = (idx >> 2) & 255;
    int ks = (idx >> 10) & 7;
    int h  = idx >> 13;
    const float* row = omega + ((size_t)h * M_ + m) * DK_ + ks * 8;
    uint32_t h0, l0, h1, l1;
    tf32_split(row[tg], h0, l0);
    tf32_split(row[tg + 4], h1, l1);
    g_omf[idx] = make_uint4(h0, h1, l0, l1);
}

// ============ mma.sync TF32 3x GEMM (unchanged) ==========================
__global__ __launch_bounds__(256) void k_gemm_mma(const float* __restrict__ A,
                                                  const float* __restrict__ Bw,
                                                  const float* __restrict__ bias,
                                                  float* __restrict__ Cp,
                                                  int mode) {
    __shared__ __align__(16) float As[2][128][20];
    __shared__ __align__(16) float Bs[2][128][20];
    const int t = threadIdx.x;
    const int lane = t & 31, wid = t >> 5;
    const int g = lane >> 2, tg = lane & 3;
    const int wm = wid >> 2, wn = wid & 3;
    const int rb = blockIdx.y * 128, cb = blockIdx.x * 128;
    constexpr int K = 1024;
    constexpr int NSLAB = K / 16;
    const float* Ap = (mode == 1) ? (const float*)g_ctx : A;

    float acc[4][4][4];
#pragma unroll
    for (int i = 0; i < 4; i++)
#pragma unroll
        for (int j = 0; j < 4; j++)
#pragma unroll
            for (int e = 0; e < 4; e++) acc[i][j][e] = 0.0f;

    {
#pragma unroll
        for (int it = 0; it < 2; it++) {
            int f = it * 256 + t;
            int r = f >> 2, q = f & 3;
            cp_async16(&As[0][r][q * 4], Ap + (size_t)(rb + r) * K + q * 4);
            cp_async16(&Bs[0][r][q * 4], Bw + (size_t)(cb + r) * K + q * 4);
        }
        asm volatile("cp.async.commit_group;" ::: "memory");
    }

    for (int sl = 0; sl < NSLAB; sl++) {
        const int st = sl & 1;
        if (sl + 1 < NSLAB) {
            const int kt = (sl + 1) * 16;
            const int ns = st ^ 1;
#pragma unroll
            for (int it = 0; it < 2; it++) {
                int f = it * 256 + t;
                int r = f >> 2, q = f & 3;
                cp_async16(&As[ns][r][q * 4], Ap + (size_t)(rb + r) * K + kt + q * 4);
                cp_async16(&Bs[ns][r][q * 4], Bw + (size_t)(cb + r) * K + kt + q * 4);
            }
            asm volatile("cp.async.commit_group;" ::: "memory");
            asm volatile("cp.async.wait_group 1;" ::: "memory");
        } else {
            asm volatile("cp.async.wait_group 0;" ::: "memory");
        }
        __syncthreads();

#pragma unroll
        for (int ks = 0; ks < 2; ks++) {
            const int k0 = ks * 8;
            uint32_t ah[4][4], al[4][4], bh[4][2], bl[4][2];
#pragma unroll
            for (int i = 0; i < 4; i++) {
                const int m0 = wm * 64 + i * 16;
                tf32_split(As[st][m0 + g    ][k0 + tg    ], ah[i][0], al[i][0]);
                tf32_split(As[st][m0 + g + 8][k0 + tg    ], ah[i][1], al[i][1]);
                tf32_split(As[st][m0 + g    ][k0 + tg + 4], ah[i][2], al[i][2]);
                tf32_split(As[st][m0 + g + 8][k0 + tg + 4], ah[i][3], al[i][3]);
            }
#pragma unroll
            for (int j = 0; j < 4; j++) {
                const int n0 = wn * 32 + j * 8;
                tf32_split(Bs[st][n0 + g][k0 + tg    ], bh[j][0], bl[j][0]);
                tf32_split(Bs[st][n0 + g][k0 + tg + 4], bh[j][1], bl[j][1]);
            }
#pragma unroll
            for (int i = 0; i < 4; i++)
#pragma unroll
                for (int j = 0; j < 4; j++) mma_tf32(acc[i][j], ah[i], bh[j]);
#pragma unroll
            for (int i = 0; i < 4; i++)
#pragma unroll
                for (int j = 0; j < 4; j++) mma_tf32(acc[i][j], ah[i], bl[j]);
#pragma unroll
            for (int i = 0; i < 4; i++)
#pragma unroll
                for (int j = 0; j < 4; j++) mma_tf32(acc[i][j], al[i], bh[j]);
        }
        __syncthreads();
    }

#pragma unroll
    for (int i = 0; i < 4; i++) {
        const int r0 = rb + wm * 64 + i * 16 + g;
#pragma unroll
        for (int j = 0; j < 4; j++) {
            const int c = cb + wn * 32 + j * 8 + tg * 2;
            const float b0 = bias[c], b1 = bias[c + 1];
            if (mode == 1) {
                *(float2*)(Cp + (size_t)r0 * 1024 + c) =
                    make_float2(acc[i][j][0] + b0, acc[i][j][1] + b1);
                *(float2*)(Cp + (size_t)(r0 + 8) * 1024 + c) =
                    make_float2(acc[i][j][2] + b0, acc[i][j][3] + b1);
            } else {
                const int which = c >> 10;
                const int hh = (c & 1023) >> 6;
                const int dk = c & 63;
#pragma unroll
                for (int half = 0; half < 2; half++) {
                    const int r = r0 + half * 8;
                    const float vv = g_valid[r];
                    const float v0 = acc[i][j][half * 2 + 0] + b0;
                    const float v1 = acc[i][j][half * 2 + 1] + b1;
                    size_t off = ((((size_t)(r >> 12)) * H_ + hh) * N_ + (r & 4095)) * DK_ + dk;
                    if (which == 0)
                        *(float2*)(g_Q + off) = make_float2(v0 * vv, v1 * vv);
                    else if (which == 1)
                        *(float2*)(g_K + off) = make_float2(v0, v1);
                    else
                        *(float2*)(g_V + off) = make_float2(v0 * vv, v1 * vv);
                }
            }
        }
    }
}

// ===================== kernel 0: mask -> valid ==========================
__global__ void k_mask(const void* __restrict__ mask) {
    __shared__ int sF, sOdd;
    const int t = threadIdx.x;
    if (t == 0) { sF = 0; sOdd = 0; }
    __syncthreads();
    const unsigned* w = (const unsigned*)mask;
    for (int i = t; i < 4096; i += 256) {
        unsigned v = w[i];
        if (v == 0x3F800000u) sF = 1;
        else if (v != 0u && v != 1u) sOdd = 1;
    }
    __syncthreads();
    if (sF) {
        const float* m = (const float*)mask;
        for (int i = t; i < B_ * N_; i += 256)
            g_valid[i] = (m[i] != 0.0f) ? 0.0f : 1.0f;
    } else if (sOdd) {
        const unsigned char* m = (const unsigned char*)mask;
        for (int i = t; i < B_ * N_; i += 256)
            g_valid[i] = m[i] ? 0.0f : 1.0f;
    } else {
        const int* m = (const int*)mask;
        for (int i = t; i < B_ * N_; i += 256)
            g_valid[i] = m[i] ? 0.0f : 1.0f;
    }
}

// ====== kernel A: phi(K) fused with S/Ksum partial accumulation =========
__global__ __launch_bounds__(256) void k_phik_spart() {
    __shared__ __align__(16) float pool[10752];   // 43 KB
    __shared__ float s_max[4][64];
    __shared__ float s_sq[64];
    float* Ts  = pool;            // [64][36] (phi phase)
    float* Stg = pool;            // [32][264] alias
    float* Vs  = pool + 8448;     // [32][72]

    const int t = threadIdx.x, lane = t & 31, wid = t >> 5;
    const int g = lane >> 2, tg = lane & 3;
    const int wm = wid >> 2, wn = wid & 3;       // phi warp grid 2m x 4n
    const int wmA = wid >> 1, wnA = wid & 1;     // spart warp grid 4m x 2n
    const int bh = blockIdx.x, ch = blockIdx.y;
    const int h = bh & (H_ - 1), bI = bh >> 4;
    const float invs = rsqrtf(256.0f + 1e-6f);

    float acc2[4][4][4];
#pragma unroll
    for (int i = 0; i < 4; i++)
#pragma unroll
        for (int j = 0; j < 4; j++)
#pragma unroll
            for (int e = 0; e < 4; e++) acc2[i][j][e] = 0.0f;
    float ksacc = 0.0f;

    for (int tile = 0; tile < 4; tile++) {
        const int n0 = ch * 256 + tile * 64;
        float acc[2][8][4];
#pragma unroll
        for (int mi = 0; mi < 2; mi++)
#pragma unroll
            for (int nj = 0; nj < 8; nj++)
#pragma unroll
                for (int e = 0; e < 4; e++) acc[mi][nj][e] = 0.0f;

        for (int kp = 0; kp < 2; kp++) {
            const int k0g = kp * 32;
            __syncthreads();
#pragma unroll
            for (int it = 0; it < 2; it++) {
                int f = it * 256 + t;
                int r = f >> 3, q = f & 7;
                float4 v = *(const float4*)(g_K + ((size_t)bh * N_ + n0 + r) * DK_ + k0g + q * 4);
                *(float4*)(Ts + r * 36 + q * 4) = v;
            }
            __syncthreads();
            if (t < 64) {
                float ssum = 0.0f;
#pragma unroll
                for (int k = 0; k < 32; k++) { float q = Ts[t * 36 + k]; ssum += q * q; }
                if (kp == 0) s_sq[t] = ssum; else s_sq[t] += ssum;
            }
#pragma unroll
            for (int ks = 0; ks < 4; ks++) {
                const int k0 = ks * 8;
                const uint4* pb = g_omf + ((size_t)(h * 8 + kp * 4 + ks) << 10);
                uint32_t ah[2][4], al[2][4], obh[8][2], obl[8][2];
#pragma unroll
                for (int mi = 0; mi < 2; mi++) {
                    const int m0 = wm * 32 + mi * 16;
                    tf32_split(Ts[(m0 + g    ) * 36 + k0 + tg    ], ah[mi][0], al[mi][0]);
                    tf32_split(Ts[(m0 + g + 8) * 36 + k0 + tg    ], ah[mi][1], al[mi][1]);
                    tf32_split(Ts[(m0 + g    ) * 36 + k0 + tg + 4], ah[mi][2], al[mi][2]);
                    tf32_split(Ts[(m0 + g + 8) * 36 + k0 + tg + 4], ah[mi][3], al[mi][3]);
                }
#pragma unroll
                for (int nj = 0; nj < 8; nj++) {
                    uint4 v = pb[(wn * 64 + nj * 8 + g) * 4 + tg];
                    obh[nj][0] = v.x; obh[nj][1] = v.y;
                    obl[nj][0] = v.z; obl[nj][1] = v.w;
                }
#pragma unroll
                for (int mi = 0; mi < 2; mi++)
#pragma unroll
                    for (int nj = 0; nj < 8; nj++) mma_tf32(acc[mi][nj], ah[mi], obh[nj]);
#pragma unroll
                for (int mi = 0; mi < 2; mi++)
#pragma unroll
                    for (int nj = 0; nj < 8; nj++) mma_tf32(acc[mi][nj], ah[mi], obl[nj]);
#pragma unroll
                for (int mi = 0; mi < 2; mi++)
#pragma unroll
                    for (int nj = 0; nj < 8; nj++) mma_tf32(acc[mi][nj], al[mi], obh[nj]);
            }
        }
#pragma unroll
        for (int mi = 0; mi < 2; mi++) {
#pragma unroll
            for (int half = 0; half < 2; half++) {
                float m = acc[mi][0][half * 2];
#pragma unroll
                for (int nj = 0; nj < 8; nj++) {
                    m = fmaxf(m, acc[mi][nj][half * 2]);
                    m = fmaxf(m, acc[mi][nj][half * 2 + 1]);
                }
                m = fmaxf(m, __shfl_xor_sync(0xffffffffu, m, 1));
                m = fmaxf(m, __shfl_xor_sync(0xffffffffu, m, 2));
                if (tg == 0) s_max[wn][wm * 32 + mi * 16 + half * 8 + g] = m;
            }
        }
        __syncthreads();

        for (int hr = 0; hr < 2; hr++) {
            if (wm == hr) {
#pragma unroll
                for (int mi = 0; mi < 2; mi++)
#pragma unroll
                for (int half = 0; half < 2; half++) {
                    const int rloc = mi * 16 + half * 8 + g;
                    const int rg = hr * 32 + rloc;
                    float rm = fmaxf(fmaxf(s_max[0][rg], s_max[1][rg]),
                                     fmaxf(s_max[2][rg], s_max[3][rg]));
                    float e = -rm - 0.5f * s_sq[rg];
                    float sc = invs * g_valid[bI * N_ + n0 + rg];
#pragma unroll
                    for (int nj = 0; nj < 8; nj++) {
                        const int col = wn * 64 + nj * 8 + tg * 2;
                        *(float2*)(Stg + rloc * 264 + col) = make_float2(
                            tf32r(fexp(acc[mi][nj][half * 2    ] + e) * sc),
                            tf32r(fexp(acc[mi][nj][half * 2 + 1] + e) * sc));
                    }
                }
            }
#pragma unroll
            for (int it = 0; it < 2; it++) {
                int f = it * 256 + t;
                int r = f >> 4, dq = f & 15;
                float4 v = *(const float4*)(g_V + ((size_t)bh * N_ + n0 + hr * 32 + r) * DK_ + dq * 4);
                v.x = tf32r(v.x); v.y = tf32r(v.y);
                v.z = tf32r(v.z); v.w = tf32r(v.w);
                *(float4*)(Vs + r * 72 + dq * 4) = v;
            }
            __syncthreads();
#pragma unroll 8
            for (int r = 0; r < 32; r++) ksacc += Stg[r * 264 + t];
            // S += Kf^T V, tf32-1x (operands pre-rounded): raw LDS fragments
#pragma unroll
            for (int ks = 0; ks < 4; ks++) {
                const int k0 = ks * 8;
                uint32_t ah[4][4], bhf[4][2];
#pragma unroll
                for (int mi = 0; mi < 4; mi++) {
                    const int m0 = wmA * 64 + mi * 16;
                    ah[mi][0] = __float_as_uint(Stg[(k0 + tg    ) * 264 + m0 + g    ]);
                    ah[mi][1] = __float_as_uint(Stg[(k0 + tg    ) * 264 + m0 + g + 8]);
                    ah[mi][2] = __float_as_uint(Stg[(k0 + tg + 4) * 264 + m0 + g    ]);
                    ah[mi][3] = __float_as_uint(Stg[(k0 + tg + 4) * 264 + m0 + g + 8]);
                }
#pragma unroll
                for (int nj = 0; nj < 4; nj++) {
                    const int n0d = wnA * 32 + nj * 8;
                    bhf[nj][0] = __float_as_uint(Vs[(k0 + tg    ) * 72 + n0d + g]);
                    bhf[nj][1] = __float_as_uint(Vs[(k0 + tg + 4) * 72 + n0d + g]);
                }
#pragma unroll
                for (int mi = 0; mi < 4; mi++)
#pragma unroll
                    for (int nj = 0; nj < 4; nj++) mma_tf32(acc2[mi][nj], ah[mi], bhf[nj]);
            }
            __syncthreads();
        }
    }

    const size_t pb = ((size_t)bh * CH_ + ch) * M_;
#pragma unroll
    for (int mi = 0; mi < 4; mi++) {
        const int feat = wmA * 64 + mi * 16 + g;
#pragma unroll
        for (int nj = 0; nj < 4; nj++) {
            const int dk = wnA * 32 + nj * 8 + tg * 2;
            *(float2*)(g_Spart + (pb + feat) * DK_ + dk) =
                make_float2(acc2[mi][nj][0], acc2[mi][nj][1]);
            *(float2*)(g_Spart + (pb + feat + 8) * DK_ + dk) =
                make_float2(acc2[mi][nj][2], acc2[mi][nj][3]);
        }
    }
    g_Kpart[pb + t] = ksacc;
}

// ============ kernel 3b: deterministic chunk reduction ===================
__global__ void k_sreduce() {
    const int tot = BH_ * M_ * (DK_ + 1);
    int idx = blockIdx.x * 256 + threadIdx.x;
    if (idx >= tot) return;
    int bh  = idx / (M_ * (DK_ + 1));
    int rem = idx % (M_ * (DK_ + 1));
    int m = rem / (DK_ + 1);
    int d = rem % (DK_ + 1);
    if (d < DK_) {
        float s = 0.0f;
#pragma unroll
        for (int c = 0; c < CH_; c++)
            s += g_Spart[(((size_t)bh * CH_ + c) * M_ + m) * DK_ + d];
        g_S[((size_t)bh * M_ + m) * DK_ + d] = s;
    } else {
        float s = 0.0f;
#pragma unroll
        for (int c = 0; c < CH_; c++)
            s += g_Kpart[((size_t)bh * CH_ + c) * M_ + m];
        g_Ksum[(size_t)bh * M_ + m] = s;
    }
}

// ====== kernel B: phi(Q) fused with ctx = (Qf S)/(Qf Ksum + eps) ========
__global__ __launch_bounds__(256) void k_phiq_ctx() {
    __shared__ __align__(16) float pool[8960];    // 35.8 KB
    __shared__ float s_max[4][64];
    __shared__ float s_sq[64];
    __shared__ float s_den[64];
    __shared__ float Kss[64];
    float* Ts  = pool;            // [64][36]
    float* Stg = pool;            // [64][68] alias
    float* Ss  = pool + 4352;     // [64][72]

    const int t = threadIdx.x, lane = t & 31, wid = t >> 5;
    const int g = lane >> 2, tg = lane & 3;
    const int wm = wid >> 2, wn = wid & 3;
    const int bh = blockIdx.x;
    const int n0 = blockIdx.y * 64;
    const int h = bh & (H_ - 1), bI = bh >> 4;
    const float invs = rsqrtf(256.0f + 1e-6f);

    float acc[2][8][4];
#pragma unroll
    for (int mi = 0; mi < 2; mi++)
#pragma unroll
        for (int nj = 0; nj < 8; nj++)
#pragma unroll
            for (int e = 0; e < 4; e++) acc[mi][nj][e] = 0.0f;
    float accC[2][2][4];
#pragma unroll
    for (int mi = 0; mi < 2; mi++)
#pragma unroll
        for (int nj = 0; nj < 2; nj++)
#pragma unroll
            for (int e = 0; e < 4; e++) accC[mi][nj][e] = 0.0f;
    float dpart = 0.0f;

    for (int kp = 0; kp < 2; kp++) {
        const int k0g = kp * 32;
        __syncthreads();
#pragma unroll
        for (int it = 0; it < 2; it++) {
            int f = it * 256 + t;
            int r = f >> 3, q = f & 7;
            float4 v = *(const float4*)(g_Q + ((size_t)bh * N_ + n0 + r) * DK_ + k0g + q * 4);
            *(float4*)(Ts + r * 36 + q * 4) = v;
        }
        __syncthreads();
        if (t < 64) {
            float ssum = 0.0f;
#pragma unroll
            for (int k = 0; k < 32; k++) { float q = Ts[t * 36 + k]; ssum += q * q; }
            if (kp == 0) s_sq[t] = ssum; else s_sq[t] += ssum;
        }
#pragma unroll
        for (int ks = 0; ks < 4; ks++) {
            const int k0 = ks * 8;
            const uint4* pb = g_omf + ((size_t)(h * 8 + kp * 4 + ks) << 10);
            uint32_t ah[2][4], al[2][4], obh[8][2], obl[8][2];
#pragma unroll
            for (int mi = 0; mi < 2; mi++) {
                const int m0 = wm * 32 + mi * 16;
                tf32_split(Ts[(m0 + g    ) * 36 + k0 + tg    ], ah[mi][0], al[mi][0]);
                tf32_split(Ts[(m0 + g + 8) * 36 + k0 + tg    ], ah[mi][1], al[mi][1]);
                tf32_split(Ts[(m0 + g    ) * 36 + k0 + tg + 4], ah[mi][2], al[mi][2]);
                tf32_split(Ts[(m0 + g + 8) * 36 + k0 + tg + 4], ah[mi][3], al[mi][3]);
            }
#pragma unroll
            for (int nj = 0; nj < 8; nj++) {
                uint4 v = pb[(wn * 64 + nj * 8 + g) * 4 + tg];
                obh[nj][0] = v.x; obh[nj][1] = v.y;
                obl[nj][0] = v.z; obl[nj][1] = v.w;
            }
#pragma unroll
            for (int mi = 0; mi < 2; mi++)
#pragma unroll
                for (int nj = 0; nj < 8; nj++) mma_tf32(acc[mi][nj], ah[mi], obh[nj]);
#pragma unroll
            for (int mi = 0; mi < 2; mi++)
#pragma unroll
                for (int nj = 0; nj < 8; nj++) mma_tf32(acc[mi][nj], ah[mi], obl[nj]);
#pragma unroll
            for (int mi = 0; mi < 2; mi++)
#pragma unroll
                for (int nj = 0; nj < 8; nj++) mma_tf32(acc[mi][nj], al[mi], obh[nj]);
        }
    }
#pragma unroll
    for (int mi = 0; mi < 2; mi++) {
#pragma unroll
        for (int half = 0; half < 2; half++) {
            float m = acc[mi][0][half * 2];
#pragma unroll
            for (int nj = 0; nj < 8; nj++) {
                m = fmaxf(m, acc[mi][nj][half * 2]);
                m = fmaxf(m, acc[mi][nj][half * 2 + 1]);
            }
            m = fmaxf(m, __shfl_xor_sync(0xffffffffu, m, 1));
            m = fmaxf(m, __shfl_xor_sync(0xffffffffu, m, 2));
            if (tg == 0) s_max[wn][wm * 32 + mi * 16 + half * 8 + g] = m;
        }
    }
    __syncthreads();

    for (int s = 0; s < 4; s++) {
        if (s) __syncthreads();
        if (wn == s) {
#pragma unroll
            for (int mi = 0; mi < 2; mi++)
#pragma unroll
            for (int half = 0; half < 2; half++) {
                const int rg = wm * 32 + mi * 16 + half * 8 + g;
                float rm = fmaxf(fmaxf(s_max[0][rg], s_max[1][rg]),
                                 fmaxf(s_max[2][rg], s_max[3][rg]));
                float e = -rm - 0.5f * s_sq[rg];
#pragma unroll
                for (int nj = 0; nj < 8; nj++) {
                    const int col = nj * 8 + tg * 2;
                    *(float2*)(Stg + rg * 68 + col) = make_float2(
                        tf32r(fexp(acc[mi][nj][half * 2    ] + e) * invs),
                        tf32r(fexp(acc[mi][nj][half * 2 + 1] + e) * invs));
                }
            }
        }
#pragma unroll
        for (int it = 0; it < 4; it++) {
            int f = it * 256 + t;
            int r = f >> 4, dq = f & 15;
            float4 v = *(const float4*)(g_S + ((size_t)bh * M_ + s * 64 + r) * DK_ + dq * 4);
            v.x = tf32r(v.x); v.y = tf32r(v.y);
            v.z = tf32r(v.z); v.w = tf32r(v.w);
            *(float4*)(Ss + r * 72 + dq * 4) = v;
        }
        if (t < 64) Kss[t] = g_Ksum[(size_t)bh * M_ + s * 64 + t];
        __syncthreads();
        {
            const int r = t >> 2, fg = (t & 3) * 16;
#pragma unroll
            for (int i = 0; i < 16; i++)
                dpart = fmaf(Stg[r * 68 + fg + i], Kss[fg + i], dpart);
        }
        // ctx += Qf_slab @ S_slab, tf32-1x raw fragments
#pragma unroll
        for (int ks = 0; ks < 8; ks++) {
            const int k0 = ks * 8;
            uint32_t ah[2][4], bhf[2][2];
#pragma unroll
            for (int mi = 0; mi < 2; mi++) {
                const int m0 = wm * 32 + mi * 16;
                ah[mi][0] = __float_as_uint(Stg[(m0 + g    ) * 68 + k0 + tg    ]);
                ah[mi][1] = __float_as_uint(Stg[(m0 + g + 8) * 68 + k0 + tg    ]);
                ah[mi][2] = __float_as_uint(Stg[(m0 + g    ) * 68 + k0 + tg + 4]);
                ah[mi][3] = __float_as_uint(Stg[(m0 + g + 8) * 68 + k0 + tg + 4]);
            }
#pragma unroll
            for (int nj = 0; nj < 2; nj++) {
                const int n0d = wn * 16 + nj * 8;
                bhf[nj][0] = __float_as_uint(Ss[(k0 + tg    ) * 72 + n0d + g]);
                bhf[nj][1] = __float_as_uint(Ss[(k0 + tg + 4) * 72 + n0d + g]);
            }
#pragma unroll
            for (int mi = 0; mi < 2; mi++)
#pragma unroll
                for (int nj = 0; nj < 2; nj++) mma_tf32(accC[mi][nj], ah[mi], bhf[nj]);
        }
    }
    dpart += __shfl_xor_sync(0xffffffffu, dpart, 1);
    dpart += __shfl_xor_sync(0xffffffffu, dpart, 2);
    if ((t & 3) == 0) s_den[t >> 2] = dpart;
    __syncthreads();

#pragma unroll
    for (int mi = 0; mi < 2; mi++) {
        const int r0 = wm * 32 + mi * 16 + g;
#pragma unroll
        for (int nj = 0; nj < 2; nj++) {
            const int dk = wn * 16 + nj * 8 + tg * 2;
#pragma unroll
            for (int half = 0; half < 2; half++) {
                const int r = r0 + half * 8;
                const float vv = g_valid[bI * N_ + n0 + r];
                const float dn = vv / (s_den[r] + 1e-6f);
                *(float2*)(g_ctx + ((size_t)bI * N_ + n0 + r) * D_ + h * DK_ + dk) =
                    make_float2(accC[mi][nj][half * 2] * dn,
                                accC[mi][nj][half * 2 + 1] * dn);
            }
        }
    }
}

// ========================= launch ========================================
extern "C" void kernel_launch(void* const* d_in, const int* in_sizes, int n_in,
                              void* d_out, int out_size) {
    (void)in_sizes; (void)n_in; (void)out_size;
    const float* x     = (const float*)d_in[0];
    const float* Wqkv  = (const float*)d_in[1];
    const float* bqkv  = (const float*)d_in[2];
    const float* Wout  = (const float*)d_in[3];
    const float* bout  = (const float*)d_in[4];
    const float* omega = (const float*)d_in[5];
    const void*  mask  = d_in[6];
    float* out = (float*)d_out;

    k_mask<<<1, 256>>>(mask);
    k_omsplit<<<512, 256>>>(omega);
    k_gemm_mma<<<dim3(24, 128), 256>>>(x, Wqkv, bqkv, nullptr, 0);
    k_phik_spart<<<dim3(BH_, CH_), 256>>>();
    {
        const int tot = BH_ * M_ * (DK_ + 1);
        k_sreduce<<<(tot + 255) / 256, 256>>>();
    }
    k_phiq_ctx<<<dim3(BH_, N_ / 64), 256>>>();
    k_gemm_mma<<<dim3(8, 128), 256>>>(x, Wout, bout, out, 1);
}